// round 5
// baseline (speedup 1.0000x reference)
#include <cuda_runtime.h>
#include <cstdint>

typedef unsigned long long u64;

#define NGEN 8192
#define NPOS 8192
#define NT   16384
#define DIM  256
#define BM   64
#define BN   64
#define NTHR 512
#define TNP  264             // Tn row stride in floats (264 mod 32 = 8 -> conflict-free)
#define STP  66              // St2 row stride in u64 units
#define TEMP_INV (-0.05f)    // -1/20

// ---------------- device scratch (no allocations allowed) ----------------
__device__ float g_tnorm[NT];

// ---------------- f32x2 helpers (FFMA2 path, sm_103a) ----------------
__device__ __forceinline__ void fma2(u64 &c, u64 a, u64 b) {
    asm("fma.rn.f32x2 %0, %1, %2, %0;" : "+l"(c) : "l"(a), "l"(b));
}
__device__ __forceinline__ float2 unpk(u64 v) {
    float2 r; asm("mov.b64 {%0, %1}, %2;" : "=f"(r.x), "=f"(r.y) : "l"(v)); return r;
}
__device__ __forceinline__ u64 dup2(float s) {
    u64 r; asm("mov.b64 %0, {%1, %1};" : "=l"(r) : "f"(s)); return r;
}

// ---------------- kernel 0: squared norms of all 16384 targets ----------------
__global__ void norm_kernel(const float* __restrict__ G, const float* __restrict__ P) {
    int warp = (blockIdx.x * blockDim.x + threadIdx.x) >> 5;
    int lane = threadIdx.x & 31;
    if (warp >= NT) return;
    const float* row = (warp < NGEN) ? (G + (size_t)warp * DIM)
                                     : (P + (size_t)(warp - NGEN) * DIM);
    float4 a = *(const float4*)(row + lane * 4);
    float4 b = *(const float4*)(row + 128 + lane * 4);
    float s = a.x*a.x + a.y*a.y + a.z*a.z + a.w*a.w
            + b.x*b.x + b.y*b.y + b.z*b.z + b.w*b.w;
#pragma unroll
    for (int o = 16; o; o >>= 1) s += __shfl_xor_sync(0xffffffffu, s, o);
    if (lane == 0) g_tnorm[warp] = s;
}

// ---------------- GEMM2 helper ----------------
// warp covers 8 m-rows x one 128-float d-half; lane owns 4 floats (2 f32x2).
__device__ __forceinline__ void gemm2_tile(u64 (&acc)[8][2],
                                           const float* __restrict__ Tn,
                                           const u64* __restrict__ St2,
                                           int m0b, int d0) {
#pragma unroll 2
    for (int n = 0; n < BN; ++n) {
        ulonglong2 tv = *(const ulonglong2*)(Tn + n * TNP + d0);   // LDS.128
        const ulonglong2* srow = (const ulonglong2*)(St2 + n * STP + m0b);
        ulonglong2 s01 = srow[0];   // uniform per warp -> broadcast
        ulonglong2 s23 = srow[1];
        ulonglong2 s45 = srow[2];
        ulonglong2 s67 = srow[3];
        fma2(acc[0][0], s01.x, tv.x);  fma2(acc[0][1], s01.x, tv.y);
        fma2(acc[1][0], s01.y, tv.x);  fma2(acc[1][1], s01.y, tv.y);
        fma2(acc[2][0], s23.x, tv.x);  fma2(acc[2][1], s23.x, tv.y);
        fma2(acc[3][0], s23.y, tv.x);  fma2(acc[3][1], s23.y, tv.y);
        fma2(acc[4][0], s45.x, tv.x);  fma2(acc[4][1], s45.x, tv.y);
        fma2(acc[5][0], s45.y, tv.x);  fma2(acc[5][1], s45.y, tv.y);
        fma2(acc[6][0], s67.x, tv.x);  fma2(acc[6][1], s67.x, tv.y);
        fma2(acc[7][0], s67.y, tv.x);  fma2(acc[7][1], s67.y, tv.y);
    }
}

// ---------------- SMEM layout ----------------
// Qt2[128][64] u64 | Tn[64][TNP] f32 | St2[64][STP] u64 | qn[64] | tnS[64] | rsred[2][64][16] | rs_s[2][64]
#define SMEM_BYTES (128*BM*8 + BN*TNP*4 + BN*STP*8 + BM*4 + BN*4 + 2*BM*16*4 + 2*BM*4)

__global__ void __launch_bounds__(NTHR, 1)
drift_main(const float* __restrict__ G, const float* __restrict__ P,
           float* __restrict__ out) {
    extern __shared__ char sm[];
    u64*   Qt2   = (u64*)sm;                       // [128][BM]  (d-pair, m)
    float* Tn    = (float*)(Qt2 + 128 * BM);       // [BN][TNP]
    u64*   St2   = (u64*)(Tn + BN * TNP);          // [BN][STP]  duplicated scores
    float* qn    = (float*)(St2 + BN * STP);       // [BM]
    float* tnS   = qn + BM;                        // [BN]
    float* rsred = tnS + BN;                       // [2][BM][16]
    float* rs_s  = rsred + 2 * BM * 16;            // [2][BM]

    const int t    = threadIdx.x;
    const int w    = t >> 5;
    const int lane = t & 31;
    const int row0 = blockIdx.x * BM;

    // GEMM1 map: 16 warps = wm(4) x wn(4); warp tile 16m x 16n.
    // lane = lm(8) x ln(4); thread: 2 m-rows, 4 n-rows (consecutive-n per instr).
    const int wm = w & 3, wn = w >> 2;
    const int lm = lane & 7, ln = lane >> 3;
    const int m0 = wm * 16 + lm * 2;
    const int nb = wn * 16 + ln;            // n_j = nb + 4*j
    const int rcol = wn * 4 + ln;           // rowsum reduction column

    // GEMM2 map: 16 warps = w8(8 m-blocks of 8) x wd(2 d-halves); lane -> 4 floats.
    const int w8 = w & 7, wd = w >> 3;
    const int m0b = w8 * 8;
    const int d0  = wd * 128 + lane * 4;

    // Load Q transposed + d-paired: Qt2[d2][m] = (g[m][2*d2], g[m][2*d2+1])
    for (int idx = t; idx < BM * 128; idx += NTHR) {
        int n  = idx >> 7;
        int d2 = idx & 127;
        Qt2[d2 * BM + n] = *(const u64*)(G + (size_t)(row0 + n) * DIM + d2 * 2);
    }
    if (t < BM) qn[t] = g_tnorm[row0 + t];

    u64 accG[8][2], accP[8][2];
#pragma unroll
    for (int i = 0; i < 8; ++i) {
        accG[i][0] = 0ull; accG[i][1] = 0ull;
        accP[i][0] = 0ull; accP[i][1] = 0ull;
    }
    float rsg[2] = {0.f, 0.f};
    float rsp[2] = {0.f, 0.f};

    const u64*   qp0 = Qt2 + m0;            // q row base (step 64 per d2)
    const float* tp0 = Tn + (nb + 0)  * TNP;
    const float* tp1 = Tn + (nb + 4)  * TNP;
    const float* tp2 = Tn + (nb + 8)  * TNP;
    const float* tp3 = Tn + (nb + 12) * TNP;

    for (int tile = 0; tile < NT / BN; ++tile) {
        const int  base  = tile * BN;
        const bool isGen = (base < NGEN);
        const float* src = isGen ? (G + (size_t)base * DIM)
                                 : (P + (size_t)(base - NGEN) * DIM);

        __syncthreads();   // previous GEMM2 done -> safe to overwrite Tn/tnS/St2
        for (int idx = t; idx < BN * (DIM / 4); idx += NTHR) {
            int n  = idx >> 6;
            int dq = idx & 63;
            *(float4*)(Tn + n * TNP + dq * 4) =
                *(const float4*)(src + (size_t)n * DIM + dq * 4);
        }
        if (t < BN) tnS[t] = g_tnorm[base + t];
        __syncthreads();

        // ---- GEMM1: scores c[2m][4n], d processed in f32x2-pairs (2 d2/step) ----
        u64 c[2][4];
#pragma unroll
        for (int i = 0; i < 2; ++i)
#pragma unroll
            for (int j = 0; j < 4; ++j) c[i][j] = 0ull;

#pragma unroll 2
        for (int p = 0; p < 64; ++p) {
            ulonglong2 t0 = *(const ulonglong2*)(tp0 + p * 4);   // d2=2p (.x), 2p+1 (.y)
            ulonglong2 t1 = *(const ulonglong2*)(tp1 + p * 4);
            ulonglong2 t2 = *(const ulonglong2*)(tp2 + p * 4);
            ulonglong2 t3 = *(const ulonglong2*)(tp3 + p * 4);
            ulonglong2 qa = *(const ulonglong2*)(qp0 + (2 * p)     * BM);
            ulonglong2 qb = *(const ulonglong2*)(qp0 + (2 * p + 1) * BM);
            fma2(c[0][0], qa.x, t0.x);  fma2(c[0][1], qa.x, t1.x);
            fma2(c[0][2], qa.x, t2.x);  fma2(c[0][3], qa.x, t3.x);
            fma2(c[1][0], qa.y, t0.x);  fma2(c[1][1], qa.y, t1.x);
            fma2(c[1][2], qa.y, t2.x);  fma2(c[1][3], qa.y, t3.x);
            fma2(c[0][0], qb.x, t0.y);  fma2(c[0][1], qb.x, t1.y);
            fma2(c[0][2], qb.x, t2.y);  fma2(c[0][3], qb.x, t3.y);
            fma2(c[1][0], qb.y, t0.y);  fma2(c[1][1], qb.y, t1.y);
            fma2(c[1][2], qb.y, t2.y);  fma2(c[1][3], qb.y, t3.y);
        }

        // ---- transform: dist -> exp weight, write duplicated scores ----
        const bool dtile = isGen && (base == row0);
#pragma unroll
        for (int i = 0; i < 2; ++i) {
            float rs_i = 0.f;
            float qni  = qn[m0 + i];
#pragma unroll
            for (int j = 0; j < 4; ++j) {
                int    nj  = nb + 4 * j;
                float2 dv  = unpk(c[i][j]);
                float  dot = dv.x + dv.y;
                float  sq  = qni + tnS[nj] - 2.0f * dot;
                float  s;
                if (sq > 0.f) s = __expf(sq * rsqrtf(sq) * TEMP_INV);
                else          s = 1.0f;
                if (dtile && (m0 + i == nj)) s = 0.f;   // diag -> exp(-5e6) = 0
                St2[nj * STP + (m0 + i)] = dup2(s);
                rs_i += s;
            }
            if (isGen) rsg[i] += rs_i; else rsp[i] += rs_i;
        }
        __syncthreads();

        // ---- GEMM2: accumulate k @ targets ----
        if (isGen) gemm2_tile(accG, Tn, St2, m0b, d0);
        else       gemm2_tile(accP, Tn, St2, m0b, d0);
    }

    // ---- reduce row sums across the 16 (wn,ln) threads per row ----
#pragma unroll
    for (int i = 0; i < 2; ++i) {
        rsred[(m0 + i) * 16 + rcol]            = rsg[i];
        rsred[BM * 16 + (m0 + i) * 16 + rcol]  = rsp[i];
    }
    __syncthreads();
    if (t < BM) {
        float sg = 0.f, sp = 0.f;
#pragma unroll
        for (int k = 0; k < 16; ++k) {
            sg += rsred[t * 16 + k];
            sp += rsred[BM * 16 + t * 16 + k];
        }
        rs_s[t]      = sg;
        rs_s[BM + t] = sp;
    }
    __syncthreads();

    // ---- combine and write out ----
#pragma unroll
    for (int i = 0; i < 8; ++i) {
        int   m  = m0b + i;
        float sg = rs_s[m];
        float sp = rs_s[BM + m];
        float2 p0 = unpk(accP[i][0]), p1 = unpk(accP[i][1]);
        float2 g0 = unpk(accG[i][0]), g1 = unpk(accG[i][1]);
        float4 o;
        o.x = sg * p0.x - sp * g0.x;
        o.y = sg * p0.y - sp * g0.y;
        o.z = sg * p1.x - sp * g1.x;
        o.w = sg * p1.y - sp * g1.y;
        *(float4*)(out + (size_t)(row0 + m) * DIM + d0) = o;
    }
}

// ---------------- launch ----------------
extern "C" void kernel_launch(void* const* d_in, const int* in_sizes, int n_in,
                              void* d_out, int out_size) {
    const float* G = (const float*)d_in[0];   // data_generated [8192,256]
    const float* P = (const float*)d_in[1];   // data_positive  [8192,256]
    float* out = (float*)d_out;               // [8192,256]

    cudaFuncSetAttribute(drift_main, cudaFuncAttributeMaxDynamicSharedMemorySize,
                         SMEM_BYTES);

    norm_kernel<<<NT / 8, 256>>>(G, P);
    drift_main<<<NGEN / BM, NTHR, SMEM_BYTES>>>(G, P, out);
}

// round 8
// speedup vs baseline: 1.9377x; 1.9377x over previous
#include <cuda_runtime.h>
#include <cuda_bf16.h>
#include <cstdint>

typedef uint32_t u32;

#define NGEN 8192
#define NPOS 8192
#define NT   16384
#define DIM  256
#define BM   64
#define BN   32
#define NTILES   512
#define GENTILES 256
#define NCTA     128
#define NTHR     512

// SMEM byte offsets
#define OF_Q    0                      // [64][264] bf16 = 33792
#define OF_SH   33792                  // [64][40]  bf16 = 5120
#define OF_SL   38912                  // 5120
#define OF_RS   44032                  // [64][4] f32 = 1024
#define OF_STG  45056
#define ST_T    0                      // [32][264] bf16 = 16896
#define ST_TTH  16896                  // [256][40] bf16 = 20480
#define ST_TTL  37376                  // 20480
#define ST_TN   57856                  // 32 f32 = 128
#define STAGE   57984
#define SMEM_SZ (OF_STG + 2*STAGE)     // 161024

// ---------------- device scratch (static, no allocations) ----------------
__device__ float g_tnorm[NT];
__device__ float g_sg[NGEN];
__device__ float g_sp[NGEN];
__device__ __align__(16) unsigned char g_Tbf[(size_t)NT * 512];          // bf16 rows [16384][256]
__device__ __align__(16) unsigned char g_Tth[(size_t)NTILES * 16384];    // [tile][256][32] bf16 hi
__device__ __align__(16) unsigned char g_Ttl[(size_t)NTILES * 16384];    // residual lo
__device__ float g_accG[(size_t)NGEN * DIM];
__device__ float g_accP[(size_t)NGEN * DIM];

// ---------------- asm helpers (baseline PTX only: sm_80-era) ----------------
__device__ __forceinline__ u32 smem_u32(const void* p) {
    u32 a; asm("{ .reg .u64 t; cvta.to.shared.u64 t, %1; cvt.u32.u64 %0, t; }"
               : "=r"(a) : "l"(p));
    return a;
}
__device__ __forceinline__ void ldsm4(u32 &r0, u32 &r1, u32 &r2, u32 &r3, u32 a) {
    asm volatile("ldmatrix.sync.aligned.m8n8.x4.shared.b16 {%0,%1,%2,%3}, [%4];"
                 : "=r"(r0), "=r"(r1), "=r"(r2), "=r"(r3) : "r"(a));
}
__device__ __forceinline__ void mma_bf16(float* c, u32 a0, u32 a1, u32 a2, u32 a3,
                                         u32 b0, u32 b1) {
    asm volatile("mma.sync.aligned.m16n8k16.row.col.f32.bf16.bf16.f32 "
                 "{%0,%1,%2,%3}, {%4,%5,%6,%7}, {%8,%9}, {%0,%1,%2,%3};"
                 : "+f"(c[0]), "+f"(c[1]), "+f"(c[2]), "+f"(c[3])
                 : "r"(a0), "r"(a1), "r"(a2), "r"(a3), "r"(b0), "r"(b1));
}
__device__ __forceinline__ void cpa16(u32 s, const void* g) {
    asm volatile("cp.async.cg.shared.global [%0], [%1], 16;" :: "r"(s), "l"(g));
}
#define CP_COMMIT() asm volatile("cp.async.commit_group;" ::: "memory")
#define CP_WAIT1()  asm volatile("cp.async.wait_group 1;"  ::: "memory")

__device__ __forceinline__ u32 pack_bf16(float lo, float hi) {
    u32 r; asm("cvt.rn.bf16x2.f32 %0, %1, %2;" : "=r"(r) : "f"(hi), "f"(lo)); return r;
}
__device__ __forceinline__ float tobf(float x) {
    return __bfloat162float(__float2bfloat16_rn(x));
}

// exp(-sqrt(sq)/20) entirely in FMA/ALU pipes (no MUFU)
__device__ __forceinline__ float score_fn(float sq, bool diag) {
    float y = __int_as_float(0x5f3759df - (__float_as_int(sq) >> 1));
    float xh = 0.5f * sq;
    y = y * (1.5f - xh * y * y);
    y = y * (1.5f - xh * y * y);          // rsqrt, rel err ~4e-6
    float d  = sq * y;                    // sqrt(sq)
    float tt = d * (-0.07213475204444817f);   // -log2(e)/20
    float k  = tt + 12582912.0f;          // 2^23 + 2^22 magic round
    int   n  = __float_as_int(k) - 0x4B400000;
    float f  = tt - (k - 12582912.0f);    // f in [-0.5, 0.5]
    float p  = 1.3333558146e-3f;
    p = fmaf(p, f, 9.6181291076e-3f);
    p = fmaf(p, f, 5.5504108664e-2f);
    p = fmaf(p, f, 2.4022650696e-1f);
    p = fmaf(p, f, 6.9314718056e-1f);
    p = fmaf(p, f, 1.0f);                 // 2^f
    float s = __int_as_float(__float_as_int(p) + (n << 23));
    if (!(sq > 1e-6f)) s = 1.0f;          // clip(sq,0) -> exp(0)
    if (diag)          s = 0.0f;          // exp(-1e8/20) == 0
    return s;
}

// ---------------- prep A: norms + bf16 row image ----------------
__global__ void prep_a(const float* __restrict__ G, const float* __restrict__ P) {
    int gw   = (blockIdx.x * blockDim.x + threadIdx.x) >> 5;
    int lane = threadIdx.x & 31;
    if (gw >= NT) return;
    const float* row = (gw < NGEN) ? (G + (size_t)gw * DIM)
                                   : (P + (size_t)(gw - NGEN) * DIM);
    float4 a = ((const float4*)row)[lane * 2];
    float4 b = ((const float4*)row)[lane * 2 + 1];
    float s = a.x*a.x + a.y*a.y + a.z*a.z + a.w*a.w
            + b.x*b.x + b.y*b.y + b.z*b.z + b.w*b.w;
#pragma unroll
    for (int o = 16; o; o >>= 1) s += __shfl_xor_sync(0xffffffffu, s, o);
    if (lane == 0) g_tnorm[gw] = s;

    uint4 v;
    v.x = pack_bf16(a.x, a.y);  v.y = pack_bf16(a.z, a.w);
    v.z = pack_bf16(b.x, b.y);  v.w = pack_bf16(b.z, b.w);
    *(uint4*)(g_Tbf + (size_t)gw * 512 + lane * 16) = v;
}

// ---------------- prep B: transposed hi/lo tile images [256][32] ----------------
__global__ void prep_tt(const float* __restrict__ G, const float* __restrict__ P) {
    __shared__ float stage[32 * 264];
    int tile = blockIdx.x;
    int base = tile * BN;
    const float* src = (base < NGEN) ? (G + (size_t)base * DIM)
                                     : (P + (size_t)(base - NGEN) * DIM);
    int t = threadIdx.x;                  // 256 threads
#pragma unroll
    for (int k = 0; k < 8; ++k) {
        int idx = t + k * 256;
        int n = idx >> 6, dq = idx & 63;
        *(float4*)(stage + n * 264 + dq * 4) = *(const float4*)(src + (size_t)n * DIM + dq * 4);
    }
    __syncthreads();
    u32* oh = (u32*)g_Tth + (size_t)tile * 4096;
    u32* ol = (u32*)g_Ttl + (size_t)tile * 4096;
#pragma unroll
    for (int k = 0; k < 16; ++k) {
        int idx = t + k * 256;            // 0..4095
        int d = idx >> 4, np = idx & 15, n = 2 * np;
        float f0 = stage[n * 264 + d];
        float f1 = stage[(n + 1) * 264 + d];
        oh[d * 16 + np] = pack_bf16(f0, f1);
        ol[d * 16 + np] = pack_bf16(f0 - tobf(f0), f1 - tobf(f1));
    }
}

// ---------------- prefetch one tile into a stage ----------------
__device__ __forceinline__ void prefetch(u32 stg, int t2, int tid) {
    const unsigned char* srcT = g_Tbf + (size_t)t2 * BN * 512;
#pragma unroll
    for (int k = 0; k < 2; ++k) {
        int c = tid + k * 512;            // 1024 chunks
        int n = c >> 5, part = c & 31;
        cpa16(stg + ST_T + n * 528 + part * 16, srcT + n * 512 + part * 16);
    }
    const unsigned char* srcH = g_Tth + (size_t)t2 * 16384;
    const unsigned char* srcL = g_Ttl + (size_t)t2 * 16384;
#pragma unroll
    for (int k = 0; k < 2; ++k) {
        int c = tid + k * 512;            // 1024 chunks each
        int d = c >> 2, part = c & 3;
        u32 off = d * 80 + part * 16;
        cpa16(stg + ST_TTH + off, srcH + c * 16);
        cpa16(stg + ST_TTL + off, srcL + c * 16);
    }
    if (tid < 8)
        cpa16(stg + ST_TN + tid * 16,
              (const unsigned char*)g_tnorm + (size_t)t2 * 128 + tid * 16);
}

// ---------------- main fused kernel ----------------
__global__ void __launch_bounds__(NTHR, 1)
drift_main(const float* __restrict__ G, const float* __restrict__ P) {
    extern __shared__ unsigned char sm[];
    const u32 smb = smem_u32(sm);
    float* rsred = (float*)(sm + OF_RS);

    const int tid  = threadIdx.x;
    const int w    = tid >> 5;
    const int lane = tid & 31;
    const int row0 = blockIdx.x * BM;

    const int wm = w & 3, wn = w >> 2;
    const int m0 = wm * 16;
    const int n0 = wn * 8;                 // GEMM1 n-block
    const int d0 = wn * 64;                // GEMM2 d-block
    const int r  = lane >> 2, c0 = 2 * (lane & 3);

    // prefetch tiles 0,1 first so they fly during Q setup
    prefetch(smb + OF_STG, 0, tid);            CP_COMMIT();
    prefetch(smb + OF_STG + STAGE, 1, tid);    CP_COMMIT();

    // Q tile f32 -> bf16 [64][264]
#pragma unroll
    for (int k = 0; k < 16; ++k) {
        int p = tid + k * 512;            // 8192 bf16x2 words
        int m = p >> 7, dp = p & 127;
        float2 v = *(const float2*)(G + (size_t)(row0 + m) * DIM + 2 * dp);
        *(u32*)(sm + OF_Q + m * 528 + dp * 4) = pack_bf16(v.x, v.y);
    }

    // row norms direct from global (race-free; L2-resident)
    const float qn0 = g_tnorm[row0 + m0 + r];
    const float qn1 = g_tnorm[row0 + m0 + r + 8];

    // static ldmatrix addresses
    const u32 aQ  = smb + OF_Q  + (m0 + (lane & 15)) * 528 + (lane >> 4) * 16;
    const u32 aSH = smb + OF_SH + (m0 + (lane & 15)) * 80  + (lane >> 4) * 16;
    const u32 aSL = smb + OF_SL + (m0 + (lane & 15)) * 80  + (lane >> 4) * 16;
    const u32 bT_off  = (n0 + (lane & 7)) * 528 + ((lane >> 3) & 3) * 16;
    const u32 bTT_off = (d0 + (lane & 7) + ((lane >> 4) & 1) * 8) * 80
                      + ((lane >> 3) & 1) * 16;

    float acc[32];
#pragma unroll
    for (int i = 0; i < 32; ++i) acc[i] = 0.f;
    float rs0 = 0.f, rs1 = 0.f;

    for (int tile = 0; tile < NTILES; ++tile) {
        CP_WAIT1();
        __syncthreads();
        const u32 stg = smb + OF_STG + (tile & 1) * STAGE;
        const float* tnS = (const float*)(sm + OF_STG + (tile & 1) * STAGE + ST_TN);
        const bool isGen = tile < GENTILES;

        // ---- GEMM1: S[64][32] = Q (bf16) @ T^T ----
        float cA[4] = {0.f, 0.f, 0.f, 0.f};
        float cB[4] = {0.f, 0.f, 0.f, 0.f};
        {
            const u32 aB = stg + ST_T + bT_off;
#pragma unroll
            for (int kk = 0; kk < 8; ++kk) {      // 32 d-elems per step
                u32 b0, b1, b2, b3, x0, x1, x2, x3, y0, y1, y2, y3;
                ldsm4(b0, b1, b2, b3, aB + kk * 64);
                ldsm4(x0, x1, x2, x3, aQ + kk * 64);
                ldsm4(y0, y1, y2, y3, aQ + kk * 64 + 32);
                mma_bf16(cA, x0, x1, x2, x3, b0, b1);
                mma_bf16(cB, y0, y1, y2, y3, b2, b3);
            }
        }

        // ---- transform: dist -> weight; write Sh/Sl; row sums ----
        {
            const int ncol  = n0 + c0;
            const int tbase = tile * BN;
            float2 tn2 = *(const float2*)(tnS + ncol);
            float dot00 = cA[0] + cB[0], dot01 = cA[1] + cB[1];
            float dot10 = cA[2] + cB[2], dot11 = cA[3] + cB[3];
            float s00 = score_fn(qn0 + tn2.x - 2.f * dot00,
                                 isGen && (tbase + ncol     == row0 + m0 + r));
            float s01 = score_fn(qn0 + tn2.y - 2.f * dot01,
                                 isGen && (tbase + ncol + 1 == row0 + m0 + r));
            float s10 = score_fn(qn1 + tn2.x - 2.f * dot10,
                                 isGen && (tbase + ncol     == row0 + m0 + r + 8));
            float s11 = score_fn(qn1 + tn2.y - 2.f * dot11,
                                 isGen && (tbase + ncol + 1 == row0 + m0 + r + 8));
            rs0 += s00 + s01;
            rs1 += s10 + s11;
            *(u32*)(sm + OF_SH + (m0 + r)     * 80 + ncol * 2) = pack_bf16(s00, s01);
            *(u32*)(sm + OF_SH + (m0 + r + 8) * 80 + ncol * 2) = pack_bf16(s10, s11);
            *(u32*)(sm + OF_SL + (m0 + r)     * 80 + ncol * 2) =
                pack_bf16(s00 - tobf(s00), s01 - tobf(s01));
            *(u32*)(sm + OF_SL + (m0 + r + 8) * 80 + ncol * 2) =
                pack_bf16(s10 - tobf(s10), s11 - tobf(s11));
        }
        __syncthreads();

        // ---- GEMM2: ACC[64][256] += Sh@Th + Sl@Th + Sh@Tl ----
        {
            u32 sh[8], sl[8];
            ldsm4(sh[0], sh[1], sh[2], sh[3], aSH);
            ldsm4(sh[4], sh[5], sh[6], sh[7], aSH + 32);
            ldsm4(sl[0], sl[1], sl[2], sl[3], aSL);
            ldsm4(sl[4], sl[5], sl[6], sl[7], aSL + 32);
            const u32 bH = stg + ST_TTH + bTT_off;
            const u32 bL = stg + ST_TTL + bTT_off;
#pragma unroll
            for (int kb = 0; kb < 2; ++kb) {
                const u32* A  = sh + 4 * kb;
                const u32* Al = sl + 4 * kb;
#pragma unroll
                for (int j = 0; j < 4; ++j) {      // d16 chunks
                    u32 h0, h1, h2, h3, l0, l1, l2, l3;
                    ldsm4(h0, h1, h2, h3, bH + j * 1280 + kb * 32);
                    float* aclo = acc + 8 * j;
                    float* achi = acc + 8 * j + 4;
                    mma_bf16(aclo, A[0],  A[1],  A[2],  A[3],  h0, h1);
                    mma_bf16(achi, A[0],  A[1],  A[2],  A[3],  h2, h3);
                    mma_bf16(aclo, Al[0], Al[1], Al[2], Al[3], h0, h1);
                    mma_bf16(achi, Al[0], Al[1], Al[2], Al[3], h2, h3);
                    ldsm4(l0, l1, l2, l3, bL + j * 1280 + kb * 32);
                    mma_bf16(aclo, A[0],  A[1],  A[2],  A[3],  l0, l1);
                    mma_bf16(achi, A[0],  A[1],  A[2],  A[3],  l2, l3);
                }
            }
        }

        // ---- phase boundaries: dump accumulators + row sums ----
        if (tile == GENTILES - 1 || tile == NTILES - 1) {
            float* gacc = (tile == GENTILES - 1) ? g_accG : g_accP;
            float* gs   = (tile == GENTILES - 1) ? g_sg   : g_sp;
#pragma unroll
            for (int j = 0; j < 8; ++j) {
                int col = d0 + j * 8 + c0;
                *(float2*)(gacc + (size_t)(row0 + m0 + r) * DIM + col) =
                    make_float2(acc[4*j], acc[4*j + 1]);
                *(float2*)(gacc + (size_t)(row0 + m0 + r + 8) * DIM + col) =
                    make_float2(acc[4*j + 2], acc[4*j + 3]);
            }
            float a = rs0 + __shfl_xor_sync(0xffffffffu, rs0, 1);
            a += __shfl_xor_sync(0xffffffffu, a, 2);
            float b = rs1 + __shfl_xor_sync(0xffffffffu, rs1, 1);
            b += __shfl_xor_sync(0xffffffffu, b, 2);
            if ((lane & 3) == 0) {
                rsred[(m0 + r) * 4 + wn]     = a;
                rsred[(m0 + r + 8) * 4 + wn] = b;
            }
            __syncthreads();
            if (tid < BM)
                gs[row0 + tid] = rsred[tid*4] + rsred[tid*4+1]
                               + rsred[tid*4+2] + rsred[tid*4+3];
#pragma unroll
            for (int i = 0; i < 32; ++i) acc[i] = 0.f;
            rs0 = 0.f; rs1 = 0.f;
        }

        __syncthreads();
        if (tile + 2 < NTILES)
            prefetch(smb + OF_STG + (tile & 1) * STAGE, tile + 2, tid);
        CP_COMMIT();
    }
}

// ---------------- combine: out = sg*accP - sp*accG ----------------
__global__ void combine_kernel(float* __restrict__ out) {
    int i = blockIdx.x * 256 + threadIdx.x;      // float4 index
    int m = i >> 6;
    float sg = g_sg[m], sp = g_sp[m];
    float4 p = ((const float4*)g_accP)[i];
    float4 g = ((const float4*)g_accG)[i];
    float4 o;
    o.x = sg * p.x - sp * g.x;
    o.y = sg * p.y - sp * g.y;
    o.z = sg * p.z - sp * g.z;
    o.w = sg * p.w - sp * g.w;
    ((float4*)out)[i] = o;
}

// ---------------- launch ----------------
extern "C" void kernel_launch(void* const* d_in, const int* in_sizes, int n_in,
                              void* d_out, int out_size) {
    const float* G = (const float*)d_in[0];   // data_generated [8192,256]
    const float* P = (const float*)d_in[1];   // data_positive  [8192,256]
    float* out = (float*)d_out;               // [8192,256]

    cudaFuncSetAttribute(drift_main, cudaFuncAttributeMaxDynamicSharedMemorySize,
                         SMEM_SZ);

    prep_a<<<NT / 8, 256>>>(G, P);
    prep_tt<<<NTILES, 256>>>(G, P);
    drift_main<<<NCTA, NTHR, SMEM_SZ>>>(G, P);
    combine_kernel<<<(NGEN * DIM / 4) / 256, 256>>>(out);
}

// round 10
// speedup vs baseline: 2.0192x; 1.0421x over previous
#include <cuda_runtime.h>
#include <cuda_bf16.h>
#include <cstdint>

typedef uint32_t u32;

#define NGEN 8192
#define NPOS 8192
#define NT   16384
#define DIM  256
#define BM   64
#define BN   32
#define NTILES   512
#define GENTILES 256
#define NCTA     128
#define NTHR     512

// SMEM byte offsets
#define OF_Q    0                      // [64][264] bf16 = 33792
#define OF_S0   33792                  // 2 x (SH 5120 + SL 5120) = 20480
#define SBUFSZ  10240
#define OF_RS   54272                  // [64][4] f32 = 1024
#define OF_RF   55296                  // [64] f32 (+pad) = 256
#define OF_STG  55552
#define ST_T    0                      // [32][264] bf16 = 16896
#define ST_TTH  16896                  // [256][40] bf16 = 20480
#define ST_TTL  37376                  // 20480
#define ST_TN   57856                  // 32 f32 = 128
#define STAGE   57984
#define SMEM_SZ (OF_STG + 3*STAGE)     // 229504

// ---------------- device scratch (static, no allocations) ----------------
__device__ float g_tnorm[NT];
__device__ float g_sg[NGEN];
__device__ __align__(16) unsigned char g_Tbf[(size_t)NT * 512];          // bf16 rows [16384][256]
__device__ __align__(16) unsigned char g_Tth[(size_t)NTILES * 16384];    // [tile][256][32] bf16 hi
__device__ __align__(16) unsigned char g_Ttl[(size_t)NTILES * 16384];    // residual lo
__device__ float g_accG[(size_t)NGEN * DIM];

// ---------------- asm helpers (baseline PTX only: sm_80-era) ----------------
__device__ __forceinline__ u32 smem_u32(const void* p) {
    u32 a; asm("{ .reg .u64 t; cvta.to.shared.u64 t, %1; cvt.u32.u64 %0, t; }"
               : "=r"(a) : "l"(p));
    return a;
}
__device__ __forceinline__ void ldsm4(u32 &r0, u32 &r1, u32 &r2, u32 &r3, u32 a) {
    asm volatile("ldmatrix.sync.aligned.m8n8.x4.shared.b16 {%0,%1,%2,%3}, [%4];"
                 : "=r"(r0), "=r"(r1), "=r"(r2), "=r"(r3) : "r"(a));
}
__device__ __forceinline__ void mma_bf16(float* c, u32 a0, u32 a1, u32 a2, u32 a3,
                                         u32 b0, u32 b1) {
    asm volatile("mma.sync.aligned.m16n8k16.row.col.f32.bf16.bf16.f32 "
                 "{%0,%1,%2,%3}, {%4,%5,%6,%7}, {%8,%9}, {%0,%1,%2,%3};"
                 : "+f"(c[0]), "+f"(c[1]), "+f"(c[2]), "+f"(c[3])
                 : "r"(a0), "r"(a1), "r"(a2), "r"(a3), "r"(b0), "r"(b1));
}
__device__ __forceinline__ void cpa16(u32 s, const void* g) {
    asm volatile("cp.async.cg.shared.global [%0], [%1], 16;" :: "r"(s), "l"(g));
}
#define CP_COMMIT() asm volatile("cp.async.commit_group;" ::: "memory")
#define CP_WAIT1()  asm volatile("cp.async.wait_group 1;"  ::: "memory")
#define CP_WAIT2()  asm volatile("cp.async.wait_group 2;"  ::: "memory")

__device__ __forceinline__ u32 pack_bf16(float lo, float hi) {
    u32 r; asm("cvt.rn.bf16x2.f32 %0, %1, %2;" : "=r"(r) : "f"(hi), "f"(lo)); return r;
}
__device__ __forceinline__ float tobf(float x) {
    return __bfloat162float(__float2bfloat16_rn(x));
}

// exp(-sqrt(sq)/20) entirely in FMA/ALU pipes (no MUFU)
__device__ __forceinline__ float score_fn(float sq, bool diag) {
    float y = __int_as_float(0x5f3759df - (__float_as_int(sq) >> 1));
    float xh = 0.5f * sq;
    y = y * (1.5f - xh * y * y);
    y = y * (1.5f - xh * y * y);          // rsqrt, rel err ~4e-6
    float d  = sq * y;                    // sqrt(sq)
    float tt = d * (-0.07213475204444817f);   // -log2(e)/20
    float k  = tt + 12582912.0f;          // 2^23 + 2^22 magic round
    int   n  = __float_as_int(k) - 0x4B400000;
    float f  = tt - (k - 12582912.0f);    // f in [-0.5, 0.5]
    float p  = 1.3333558146e-3f;
    p = fmaf(p, f, 9.6181291076e-3f);
    p = fmaf(p, f, 5.5504108664e-2f);
    p = fmaf(p, f, 2.4022650696e-1f);
    p = fmaf(p, f, 6.9314718056e-1f);
    p = fmaf(p, f, 1.0f);                 // 2^f
    float s = __int_as_float(__float_as_int(p) + (n << 23));
    if (!(sq > 1e-6f)) s = 1.0f;          // clip(sq,0) -> exp(0)
    if (diag)          s = 0.0f;          // exp(-1e8/20) == 0
    return s;
}

// ---------------- prep A: norms + bf16 row image ----------------
__global__ void prep_a(const float* __restrict__ G, const float* __restrict__ P) {
    int gw   = (blockIdx.x * blockDim.x + threadIdx.x) >> 5;
    int lane = threadIdx.x & 31;
    if (gw >= NT) return;
    const float* row = (gw < NGEN) ? (G + (size_t)gw * DIM)
                                   : (P + (size_t)(gw - NGEN) * DIM);
    float4 a = ((const float4*)row)[lane * 2];
    float4 b = ((const float4*)row)[lane * 2 + 1];
    float s = a.x*a.x + a.y*a.y + a.z*a.z + a.w*a.w
            + b.x*b.x + b.y*b.y + b.z*b.z + b.w*b.w;
#pragma unroll
    for (int o = 16; o; o >>= 1) s += __shfl_xor_sync(0xffffffffu, s, o);
    if (lane == 0) g_tnorm[gw] = s;

    uint4 v;
    v.x = pack_bf16(a.x, a.y);  v.y = pack_bf16(a.z, a.w);
    v.z = pack_bf16(b.x, b.y);  v.w = pack_bf16(b.z, b.w);
    *(uint4*)(g_Tbf + (size_t)gw * 512 + lane * 16) = v;
}

// ---------------- prep B: transposed hi/lo tile images [256][32] ----------------
__global__ void prep_tt(const float* __restrict__ G, const float* __restrict__ P) {
    __shared__ float stage[32 * 264];
    int tile = blockIdx.x;
    int base = tile * BN;
    const float* src = (base < NGEN) ? (G + (size_t)base * DIM)
                                     : (P + (size_t)(base - NGEN) * DIM);
    int t = threadIdx.x;                  // 256 threads
#pragma unroll
    for (int k = 0; k < 8; ++k) {
        int idx = t + k * 256;
        int n = idx >> 6, dq = idx & 63;
        *(float4*)(stage + n * 264 + dq * 4) = *(const float4*)(src + (size_t)n * DIM + dq * 4);
    }
    __syncthreads();
    u32* oh = (u32*)g_Tth + (size_t)tile * 4096;
    u32* ol = (u32*)g_Ttl + (size_t)tile * 4096;
#pragma unroll
    for (int k = 0; k < 16; ++k) {
        int idx = t + k * 256;            // 0..4095
        int d = idx >> 4, np = idx & 15, n = 2 * np;
        float f0 = stage[n * 264 + d];
        float f1 = stage[(n + 1) * 264 + d];
        oh[d * 16 + np] = pack_bf16(f0, f1);
        ol[d * 16 + np] = pack_bf16(f0 - tobf(f0), f1 - tobf(f1));
    }
}

// ---------------- prefetch one tile into a stage ----------------
__device__ __forceinline__ void prefetch(u32 stg, int t2, int tid) {
    const unsigned char* srcT = g_Tbf + (size_t)t2 * BN * 512;
#pragma unroll
    for (int k = 0; k < 2; ++k) {
        int c = tid + k * 512;            // 1024 chunks
        int n = c >> 5, part = c & 31;
        cpa16(stg + ST_T + n * 528 + part * 16, srcT + n * 512 + part * 16);
    }
    const unsigned char* srcH = g_Tth + (size_t)t2 * 16384;
    const unsigned char* srcL = g_Ttl + (size_t)t2 * 16384;
#pragma unroll
    for (int k = 0; k < 2; ++k) {
        int c = tid + k * 512;            // 1024 chunks each
        int d = c >> 2, part = c & 3;
        u32 off = d * 80 + part * 16;
        cpa16(stg + ST_TTH + off, srcH + c * 16);
        cpa16(stg + ST_TTL + off, srcL + c * 16);
    }
    if (tid < 8)
        cpa16(stg + ST_TN + tid * 16,
              (const unsigned char*)g_tnorm + (size_t)t2 * 128 + tid * 16);
}

// ---------------- GEMM1: scores for one tile ----------------
__device__ __forceinline__ void do_gemm1(u32 stg, u32 aQ, u32 bT_off,
                                         float* cA, float* cB) {
    const u32 aB = stg + ST_T + bT_off;
#pragma unroll
    for (int kk = 0; kk < 8; ++kk) {      // 32 d-elems per step
        u32 b0, b1, b2, b3, x0, x1, x2, x3, y0, y1, y2, y3;
        ldsm4(b0, b1, b2, b3, aB + kk * 64);
        ldsm4(x0, x1, x2, x3, aQ + kk * 64);
        ldsm4(y0, y1, y2, y3, aQ + kk * 64 + 32);
        mma_bf16(cA, x0, x1, x2, x3, b0, b1);
        mma_bf16(cB, y0, y1, y2, y3, b2, b3);
    }
}

// ---------------- GEMM2: acc += Sh@Th + Sl@Th + Sh@Tl ----------------
__device__ __forceinline__ void do_gemm2(u32 stg, u32 aSH, u32 aSL, u32 bTT_off,
                                         float* acc) {
    u32 sh[8], sl[8];
    ldsm4(sh[0], sh[1], sh[2], sh[3], aSH);
    ldsm4(sh[4], sh[5], sh[6], sh[7], aSH + 32);
    ldsm4(sl[0], sl[1], sl[2], sl[3], aSL);
    ldsm4(sl[4], sl[5], sl[6], sl[7], aSL + 32);
    const u32 bH = stg + ST_TTH + bTT_off;
    const u32 bL = stg + ST_TTL + bTT_off;
#pragma unroll
    for (int kb = 0; kb < 2; ++kb) {
        const u32* A  = sh + 4 * kb;
        const u32* Al = sl + 4 * kb;
#pragma unroll
        for (int j = 0; j < 4; ++j) {      // d16 chunks
            u32 h0, h1, h2, h3, l0, l1, l2, l3;
            ldsm4(h0, h1, h2, h3, bH + j * 1280 + kb * 32);
            float* aclo = acc + 8 * j;
            float* achi = acc + 8 * j + 4;
            mma_bf16(aclo, A[0],  A[1],  A[2],  A[3],  h0, h1);
            mma_bf16(achi, A[0],  A[1],  A[2],  A[3],  h2, h3);
            mma_bf16(aclo, Al[0], Al[1], Al[2], Al[3], h0, h1);
            mma_bf16(achi, Al[0], Al[1], Al[2], Al[3], h2, h3);
            ldsm4(l0, l1, l2, l3, bL + j * 1280 + kb * 32);
            mma_bf16(aclo, A[0],  A[1],  A[2],  A[3],  l0, l1);
            mma_bf16(achi, A[0],  A[1],  A[2],  A[3],  l2, l3);
        }
    }
}

// ---------------- main fused kernel ----------------
__global__ void __launch_bounds__(NTHR, 1)
drift_main(const float* __restrict__ G, const float* __restrict__ P,
           float* __restrict__ out) {
    extern __shared__ unsigned char sm[];
    const u32 smb = smem_u32(sm);
    float* rsred = (float*)(sm + OF_RS);
    float* rsfin = (float*)(sm + OF_RF);

    const int tid  = threadIdx.x;
    const int w    = tid >> 5;
    const int lane = tid & 31;
    const int row0 = blockIdx.x * BM;

    const int wm = w & 3, wn = w >> 2;
    const int m0 = wm * 16;
    const int n0 = wn * 8;                 // GEMM1 n-block
    const int d0 = wn * 64;                // GEMM2 d-block
    const int r  = lane >> 2, c0 = 2 * (lane & 3);

    // prefetch tiles 0,1,2 (3 stages)
    prefetch(smb + OF_STG,             0, tid);  CP_COMMIT();
    prefetch(smb + OF_STG + STAGE,     1, tid);  CP_COMMIT();
    prefetch(smb + OF_STG + 2 * STAGE, 2, tid);  CP_COMMIT();

    // Q tile f32 -> bf16 [64][264]
#pragma unroll
    for (int k = 0; k < 16; ++k) {
        int p = tid + k * 512;            // 8192 bf16x2 words
        int m = p >> 7, dp = p & 127;
        float2 v = *(const float2*)(G + (size_t)(row0 + m) * DIM + 2 * dp);
        *(u32*)(sm + OF_Q + m * 528 + dp * 4) = pack_bf16(v.x, v.y);
    }

    // row norms direct from global (race-free; L2-resident)
    const float qn0 = g_tnorm[row0 + m0 + r];
    const float qn1 = g_tnorm[row0 + m0 + r + 8];

    // static ldmatrix address components
    const u32 aQ     = smb + OF_Q + (m0 + (lane & 15)) * 528 + (lane >> 4) * 16;
    const u32 aS_off = (m0 + (lane & 15)) * 80 + (lane >> 4) * 16;
    const u32 bT_off  = (n0 + (lane & 7)) * 528 + ((lane >> 3) & 3) * 16;
    const u32 bTT_off = (d0 + (lane & 7) + ((lane >> 4) & 1) * 8) * 80
                      + ((lane >> 3) & 1) * 16;

    float acc[32];
#pragma unroll
    for (int i = 0; i < 32; ++i) acc[i] = 0.f;
    float rsg0 = 0.f, rsg1 = 0.f, rsp0 = 0.f, rsp1 = 0.f;

    // ---- transform helper (lambda) ----
    auto transform = [&](int tile, int sbuf, const float* tnS,
                         const float* cA, const float* cB) {
        const int ncol  = n0 + c0;
        const int tbase = tile * BN;
        const bool isGen = tile < GENTILES;
        float2 tn2 = *(const float2*)(tnS + ncol);
        float dot00 = cA[0] + cB[0], dot01 = cA[1] + cB[1];
        float dot10 = cA[2] + cB[2], dot11 = cA[3] + cB[3];
        float s00 = score_fn(qn0 + tn2.x - 2.f * dot00,
                             isGen && (tbase + ncol     == row0 + m0 + r));
        float s01 = score_fn(qn0 + tn2.y - 2.f * dot01,
                             isGen && (tbase + ncol + 1 == row0 + m0 + r));
        float s10 = score_fn(qn1 + tn2.x - 2.f * dot10,
                             isGen && (tbase + ncol     == row0 + m0 + r + 8));
        float s11 = score_fn(qn1 + tn2.y - 2.f * dot11,
                             isGen && (tbase + ncol + 1 == row0 + m0 + r + 8));
        if (isGen) { rsg0 += s00 + s01; rsg1 += s10 + s11; }
        else       { rsp0 += s00 + s01; rsp1 += s10 + s11; }
        *(u32*)(sm + sbuf + (m0 + r)     * 80 + ncol * 2) = pack_bf16(s00, s01);
        *(u32*)(sm + sbuf + (m0 + r + 8) * 80 + ncol * 2) = pack_bf16(s10, s11);
        *(u32*)(sm + sbuf + 5120 + (m0 + r)     * 80 + ncol * 2) =
            pack_bf16(s00 - tobf(s00), s01 - tobf(s01));
        *(u32*)(sm + sbuf + 5120 + (m0 + r + 8) * 80 + ncol * 2) =
            pack_bf16(s10 - tobf(s10), s11 - tobf(s11));
    };

    // ---- prologue: GEMM1(0) + transform(0) -> S buf0 ----
    CP_WAIT2();
    __syncthreads();
    {
        float cA[4] = {0.f, 0.f, 0.f, 0.f};
        float cB[4] = {0.f, 0.f, 0.f, 0.f};
        do_gemm1(smb + OF_STG, aQ, bT_off, cA, cB);
        transform(0, OF_S0, (const float*)(sm + OF_STG + ST_TN), cA, cB);
    }

    // ---- main pipelined loop: GEMM1(t+1) || GEMM2(t) ----
    int st1 = 1;                            // (t+1) % 3
    for (int t = 0; t < NTILES - 1; ++t) {
        CP_WAIT1();                         // tile t+1 data resident (own part)
        __syncthreads();                    // cross-warp: data + S visible

        const u32 stg_n = smb + OF_STG + (u32)st1 * STAGE;     // tile t+1
        int st0 = st1 - 1; if (st0 < 0) st0 = 2;               // t % 3
        const u32 stg_c = smb + OF_STG + (u32)st0 * STAGE;     // tile t

        // GEMM1(t+1) + transform -> S[(t+1)&1]
        {
            float cA[4] = {0.f, 0.f, 0.f, 0.f};
            float cB[4] = {0.f, 0.f, 0.f, 0.f};
            do_gemm1(stg_n, aQ, bT_off, cA, cB);
            transform(t + 1, OF_S0 + ((t + 1) & 1) * SBUFSZ,
                      (const float*)(sm + OF_STG + st1 * STAGE + ST_TN), cA, cB);
        }

        // GEMM2(t) from S[t&1]
        {
            const int sb = OF_S0 + (t & 1) * SBUFSZ;
            do_gemm2(stg_c, smb + sb + aS_off, smb + sb + 5120 + aS_off,
                     bTT_off, acc);
        }

        // gen-phase boundary: dump accG + row sums
        if (t == GENTILES - 1) {
#pragma unroll
            for (int j = 0; j < 8; ++j) {
                int col = d0 + j * 8 + c0;
                *(float2*)(g_accG + (size_t)(row0 + m0 + r) * DIM + col) =
                    make_float2(acc[4*j], acc[4*j + 1]);
                *(float2*)(g_accG + (size_t)(row0 + m0 + r + 8) * DIM + col) =
                    make_float2(acc[4*j + 2], acc[4*j + 3]);
            }
            float a = rsg0 + __shfl_xor_sync(0xffffffffu, rsg0, 1);
            a += __shfl_xor_sync(0xffffffffu, a, 2);
            float b = rsg1 + __shfl_xor_sync(0xffffffffu, rsg1, 1);
            b += __shfl_xor_sync(0xffffffffu, b, 2);
            if ((lane & 3) == 0) {
                rsred[(m0 + r) * 4 + wn]     = a;
                rsred[(m0 + r + 8) * 4 + wn] = b;
            }
            __syncthreads();
            if (tid < BM)
                g_sg[row0 + tid] = rsred[tid*4] + rsred[tid*4+1]
                                 + rsred[tid*4+2] + rsred[tid*4+3];
#pragma unroll
            for (int i = 0; i < 32; ++i) acc[i] = 0.f;
        }

        __syncthreads();                    // all reads of stage t%3 done
        if (t + 3 < NTILES)
            prefetch(smb + OF_STG + (u32)st0 * STAGE, t + 3, tid);
        CP_COMMIT();

        st1++; if (st1 == 3) st1 = 0;
    }

    // ---- epilogue: GEMM2(last tile), reduce pos sums, write output ----
    {
        // tile 511 lives in stage (NTILES-1) % 3  (R9 bug: used post-loop st1 == 2)
        const u32 stg_c = smb + OF_STG + (u32)((NTILES - 1) % 3) * STAGE;
        const int sb = OF_S0 + ((NTILES - 1) & 1) * SBUFSZ;
        do_gemm2(stg_c, smb + sb + aS_off, smb + sb + 5120 + aS_off,
                 bTT_off, acc);
    }
    {
        float a = rsp0 + __shfl_xor_sync(0xffffffffu, rsp0, 1);
        a += __shfl_xor_sync(0xffffffffu, a, 2);
        float b = rsp1 + __shfl_xor_sync(0xffffffffu, rsp1, 1);
        b += __shfl_xor_sync(0xffffffffu, b, 2);
        if ((lane & 3) == 0) {
            rsred[(m0 + r) * 4 + wn]     = a;
            rsred[(m0 + r + 8) * 4 + wn] = b;
        }
        __syncthreads();
        if (tid < BM)
            rsfin[tid] = rsred[tid*4] + rsred[tid*4+1]
                       + rsred[tid*4+2] + rsred[tid*4+3];
        __syncthreads();

        const float sp0 = rsfin[m0 + r];
        const float sp1 = rsfin[m0 + r + 8];
        const float sg0 = g_sg[row0 + m0 + r];
        const float sg1 = g_sg[row0 + m0 + r + 8];
#pragma unroll
        for (int j = 0; j < 8; ++j) {
            int col = d0 + j * 8 + c0;
            float2 gv0 = *(const float2*)(g_accG + (size_t)(row0 + m0 + r) * DIM + col);
            float2 gv1 = *(const float2*)(g_accG + (size_t)(row0 + m0 + r + 8) * DIM + col);
            float2 o0, o1;
            o0.x = sg0 * acc[4*j]     - sp0 * gv0.x;
            o0.y = sg0 * acc[4*j + 1] - sp0 * gv0.y;
            o1.x = sg1 * acc[4*j + 2] - sp1 * gv1.x;
            o1.y = sg1 * acc[4*j + 3] - sp1 * gv1.y;
            *(float2*)(out + (size_t)(row0 + m0 + r) * DIM + col)     = o0;
            *(float2*)(out + (size_t)(row0 + m0 + r + 8) * DIM + col) = o1;
        }
    }
}

// ---------------- launch ----------------
extern "C" void kernel_launch(void* const* d_in, const int* in_sizes, int n_in,
                              void* d_out, int out_size) {
    const float* G = (const float*)d_in[0];   // data_generated [8192,256]
    const float* P = (const float*)d_in[1];   // data_positive  [8192,256]
    float* out = (float*)d_out;               // [8192,256]

    cudaFuncSetAttribute(drift_main, cudaFuncAttributeMaxDynamicSharedMemorySize,
                         SMEM_SZ);

    prep_a<<<NT / 8, 256>>>(G, P);
    prep_tt<<<NTILES, 256>>>(G, P);
    drift_main<<<NCTA, NTHR, SMEM_SZ>>>(G, P, out);
}

// round 11
// speedup vs baseline: 4.4025x; 2.1803x over previous
#include <cuda_runtime.h>
#include <cuda_fp16.h>
#include <cstdint>

typedef uint32_t u32;

#define NGEN 8192
#define NPOS 8192
#define NT   16384
#define DIM  256
#define BM   64
#define BN   32
#define NTILES   512
#define GENTILES 256
#define NCTA     128
#define NTHR     512

// SMEM byte offsets
#define OF_Q    0                      // [64][264] f16 = 33792
#define OF_S0   33792                  // 2 x (SH 5120) ping-pong = 10240
#define SBUFSZ  5120
#define OF_RS   44032                  // [64][4] f32 = 1024
#define OF_RF   45056                  // [64] f32 (+pad) = 256
#define OF_STG  45312
#define ST_T    0                      // [32][264] f16 = 16896
#define ST_TT   16896                  // [256][40B] f16 = 20480
#define ST_TN   37376                  // 32 f32 = 128
#define STAGE   37504
#define SMEM_SZ (OF_STG + 3*STAGE)     // 157824

// ---------------- device scratch (static, no allocations) ----------------
__device__ float g_tnorm[NT];
__device__ float g_sg[NGEN];
__device__ __align__(16) unsigned char g_Tbf[(size_t)NT * 512];          // f16 rows [16384][256]
__device__ __align__(16) unsigned char g_Tth[(size_t)NTILES * 16384];    // [tile][256][16u32] f16 T^T
__device__ float g_accG[(size_t)NGEN * DIM];

// ---------------- asm helpers (baseline PTX only: sm_80-era) ----------------
__device__ __forceinline__ u32 smem_u32(const void* p) {
    u32 a; asm("{ .reg .u64 t; cvta.to.shared.u64 t, %1; cvt.u32.u64 %0, t; }"
               : "=r"(a) : "l"(p));
    return a;
}
__device__ __forceinline__ void ldsm4(u32 &r0, u32 &r1, u32 &r2, u32 &r3, u32 a) {
    asm volatile("ldmatrix.sync.aligned.m8n8.x4.shared.b16 {%0,%1,%2,%3}, [%4];"
                 : "=r"(r0), "=r"(r1), "=r"(r2), "=r"(r3) : "r"(a));
}
__device__ __forceinline__ void mma_f16(float* c, u32 a0, u32 a1, u32 a2, u32 a3,
                                        u32 b0, u32 b1) {
    asm volatile("mma.sync.aligned.m16n8k16.row.col.f32.f16.f16.f32 "
                 "{%0,%1,%2,%3}, {%4,%5,%6,%7}, {%8,%9}, {%0,%1,%2,%3};"
                 : "+f"(c[0]), "+f"(c[1]), "+f"(c[2]), "+f"(c[3])
                 : "r"(a0), "r"(a1), "r"(a2), "r"(a3), "r"(b0), "r"(b1));
}
__device__ __forceinline__ void cpa16(u32 s, const void* g) {
    asm volatile("cp.async.cg.shared.global [%0], [%1], 16;" :: "r"(s), "l"(g));
}
#define CP_COMMIT() asm volatile("cp.async.commit_group;" ::: "memory")
#define CP_WAIT1()  asm volatile("cp.async.wait_group 1;"  ::: "memory")
#define CP_WAIT2()  asm volatile("cp.async.wait_group 2;"  ::: "memory")

__device__ __forceinline__ u32 pack_f16(float lo, float hi) {
    __half2 h = __floats2half2_rn(lo, hi);
    return *(u32*)&h;
}

// exp(-sqrt(sq)/20) entirely in FMA/ALU pipes (no MUFU)
__device__ __forceinline__ float score_fn(float sq, bool diag) {
    float y = __int_as_float(0x5f3759df - (__float_as_int(sq) >> 1));
    float xh = 0.5f * sq;
    y = y * (1.5f - xh * y * y);
    y = y * (1.5f - xh * y * y);          // rsqrt, rel err ~4e-6
    float d  = sq * y;                    // sqrt(sq)
    float tt = d * (-0.07213475204444817f);   // -log2(e)/20
    float k  = tt + 12582912.0f;          // 2^23 + 2^22 magic round
    int   n  = __float_as_int(k) - 0x4B400000;
    float f  = tt - (k - 12582912.0f);    // f in [-0.5, 0.5]
    float p  = 1.3333558146e-3f;
    p = fmaf(p, f, 9.6181291076e-3f);
    p = fmaf(p, f, 5.5504108664e-2f);
    p = fmaf(p, f, 2.4022650696e-1f);
    p = fmaf(p, f, 6.9314718056e-1f);
    p = fmaf(p, f, 1.0f);                 // 2^f
    float s = __int_as_float(__float_as_int(p) + (n << 23));
    if (!(sq > 1e-6f)) s = 1.0f;          // clip(sq,0) -> exp(0)
    if (diag)          s = 0.0f;          // exp(-1e8/20) == 0
    return s;
}

// ---------------- prep A: norms + f16 row image ----------------
__global__ void prep_a(const float* __restrict__ G, const float* __restrict__ P) {
    int gw   = (blockIdx.x * blockDim.x + threadIdx.x) >> 5;
    int lane = threadIdx.x & 31;
    if (gw >= NT) return;
    const float* row = (gw < NGEN) ? (G + (size_t)gw * DIM)
                                   : (P + (size_t)(gw - NGEN) * DIM);
    float4 a = ((const float4*)row)[lane * 2];
    float4 b = ((const float4*)row)[lane * 2 + 1];
    float s = a.x*a.x + a.y*a.y + a.z*a.z + a.w*a.w
            + b.x*b.x + b.y*b.y + b.z*b.z + b.w*b.w;
#pragma unroll
    for (int o = 16; o; o >>= 1) s += __shfl_xor_sync(0xffffffffu, s, o);
    if (lane == 0) g_tnorm[gw] = s;

    uint4 v;
    v.x = pack_f16(a.x, a.y);  v.y = pack_f16(a.z, a.w);
    v.z = pack_f16(b.x, b.y);  v.w = pack_f16(b.z, b.w);
    *(uint4*)(g_Tbf + (size_t)gw * 512 + lane * 16) = v;
}

// ---------------- prep B: transposed f16 tile images [256][32] ----------------
__global__ void prep_tt(const float* __restrict__ G, const float* __restrict__ P) {
    __shared__ float stage[32 * 264];
    int tile = blockIdx.x;
    int base = tile * BN;
    const float* src = (base < NGEN) ? (G + (size_t)base * DIM)
                                     : (P + (size_t)(base - NGEN) * DIM);
    int t = threadIdx.x;                  // 256 threads
#pragma unroll
    for (int k = 0; k < 8; ++k) {
        int idx = t + k * 256;
        int n = idx >> 6, dq = idx & 63;
        *(float4*)(stage + n * 264 + dq * 4) = *(const float4*)(src + (size_t)n * DIM + dq * 4);
    }
    __syncthreads();
    u32* oh = (u32*)g_Tth + (size_t)tile * 4096;
#pragma unroll
    for (int k = 0; k < 16; ++k) {
        int idx = t + k * 256;            // 0..4095
        int d = idx >> 4, np = idx & 15, n = 2 * np;
        float f0 = stage[n * 264 + d];
        float f1 = stage[(n + 1) * 264 + d];
        oh[d * 16 + np] = pack_f16(f0, f1);
    }
}

// ---------------- prefetch one tile into a stage ----------------
__device__ __forceinline__ void prefetch(u32 stg, int t2, int tid) {
    const unsigned char* srcT = g_Tbf + (size_t)t2 * BN * 512;
#pragma unroll
    for (int k = 0; k < 2; ++k) {
        int c = tid + k * 512;            // 1024 chunks
        int n = c >> 5, part = c & 31;
        cpa16(stg + ST_T + n * 528 + part * 16, srcT + n * 512 + part * 16);
    }
    const unsigned char* srcH = g_Tth + (size_t)t2 * 16384;
#pragma unroll
    for (int k = 0; k < 2; ++k) {
        int c = tid + k * 512;            // 1024 chunks
        int d = c >> 2, part = c & 3;
        cpa16(stg + ST_TT + d * 80 + part * 16, srcH + c * 16);
    }
    if (tid < 8)
        cpa16(stg + ST_TN + tid * 16,
              (const unsigned char*)g_tnorm + (size_t)t2 * 128 + tid * 16);
}

// ---------------- GEMM1: scores for one tile ----------------
__device__ __forceinline__ void do_gemm1(u32 stg, u32 aQ, u32 bT_off,
                                         float* cA, float* cB) {
    const u32 aB = stg + ST_T + bT_off;
#pragma unroll
    for (int kk = 0; kk < 8; ++kk) {      // 32 d-elems per step
        u32 b0, b1, b2, b3, x0, x1, x2, x3, y0, y1, y2, y3;
        ldsm4(b0, b1, b2, b3, aB + kk * 64);
        ldsm4(x0, x1, x2, x3, aQ + kk * 64);
        ldsm4(y0, y1, y2, y3, aQ + kk * 64 + 32);
        mma_f16(cA, x0, x1, x2, x3, b0, b1);
        mma_f16(cB, y0, y1, y2, y3, b2, b3);
    }
}

// ---------------- GEMM2: acc += S @ T  (single-pass f16) ----------------
__device__ __forceinline__ void do_gemm2(u32 stg, u32 aSH, u32 bTT_off,
                                         float* acc) {
    u32 sh[8];
    ldsm4(sh[0], sh[1], sh[2], sh[3], aSH);
    ldsm4(sh[4], sh[5], sh[6], sh[7], aSH + 32);
    const u32 bH = stg + ST_TT + bTT_off;
#pragma unroll
    for (int kb = 0; kb < 2; ++kb) {
        const u32* A = sh + 4 * kb;
#pragma unroll
        for (int j = 0; j < 4; ++j) {      // d16 chunks
            u32 h0, h1, h2, h3;
            ldsm4(h0, h1, h2, h3, bH + j * 1280 + kb * 32);
            mma_f16(acc + 8 * j,     A[0], A[1], A[2], A[3], h0, h1);
            mma_f16(acc + 8 * j + 4, A[0], A[1], A[2], A[3], h2, h3);
        }
    }
}

// ---------------- main fused kernel ----------------
__global__ void __launch_bounds__(NTHR, 1)
drift_main(const float* __restrict__ G, const float* __restrict__ P,
           float* __restrict__ out) {
    extern __shared__ unsigned char sm[];
    const u32 smb = smem_u32(sm);
    float* rsred = (float*)(sm + OF_RS);
    float* rsfin = (float*)(sm + OF_RF);

    const int tid  = threadIdx.x;
    const int lane = tid & 31;
    const int w    = tid >> 5;
    const int row0 = blockIdx.x * BM;

    const int wm = w & 3, wn = w >> 2;
    const int m0 = wm * 16;
    const int n0 = wn * 8;                 // GEMM1 n-block
    const int d0 = wn * 64;                // GEMM2 d-block
    const int r  = lane >> 2, c0 = 2 * (lane & 3);

    // prefetch tiles 0,1,2 (3 stages)
    prefetch(smb + OF_STG,             0, tid);  CP_COMMIT();
    prefetch(smb + OF_STG + STAGE,     1, tid);  CP_COMMIT();
    prefetch(smb + OF_STG + 2 * STAGE, 2, tid);  CP_COMMIT();

    // Q tile f32 -> f16 [64][264]
#pragma unroll
    for (int k = 0; k < 16; ++k) {
        int p = tid + k * 512;            // 8192 f16x2 words
        int m = p >> 7, dp = p & 127;
        float2 v = *(const float2*)(G + (size_t)(row0 + m) * DIM + 2 * dp);
        *(u32*)(sm + OF_Q + m * 528 + dp * 4) = pack_f16(v.x, v.y);
    }

    // row norms direct from global (race-free; L2-resident)
    const float qn0 = g_tnorm[row0 + m0 + r];
    const float qn1 = g_tnorm[row0 + m0 + r + 8];

    // static ldmatrix address components
    const u32 aQ     = smb + OF_Q + (m0 + (lane & 15)) * 528 + (lane >> 4) * 16;
    const u32 aS_off = (m0 + (lane & 15)) * 80 + (lane >> 4) * 16;
    const u32 bT_off  = (n0 + (lane & 7)) * 528 + ((lane >> 3) & 3) * 16;
    const u32 bTT_off = (d0 + (lane & 7) + ((lane >> 4) & 1) * 8) * 80
                      + ((lane >> 3) & 1) * 16;

    float acc[32];
#pragma unroll
    for (int i = 0; i < 32; ++i) acc[i] = 0.f;
    float rsg0 = 0.f, rsg1 = 0.f, rsp0 = 0.f, rsp1 = 0.f;

    // ---- transform helper (lambda) ----
    auto transform = [&](int tile, int sbuf, const float* tnS,
                         const float* cA, const float* cB) {
        const int ncol  = n0 + c0;
        const int tbase = tile * BN;
        const bool isGen = tile < GENTILES;
        float2 tn2 = *(const float2*)(tnS + ncol);
        float dot00 = cA[0] + cB[0], dot01 = cA[1] + cB[1];
        float dot10 = cA[2] + cB[2], dot11 = cA[3] + cB[3];
        float s00 = score_fn(qn0 + tn2.x - 2.f * dot00,
                             isGen && (tbase + ncol     == row0 + m0 + r));
        float s01 = score_fn(qn0 + tn2.y - 2.f * dot01,
                             isGen && (tbase + ncol + 1 == row0 + m0 + r));
        float s10 = score_fn(qn1 + tn2.x - 2.f * dot10,
                             isGen && (tbase + ncol     == row0 + m0 + r + 8));
        float s11 = score_fn(qn1 + tn2.y - 2.f * dot11,
                             isGen && (tbase + ncol + 1 == row0 + m0 + r + 8));
        if (isGen) { rsg0 += s00 + s01; rsg1 += s10 + s11; }
        else       { rsp0 += s00 + s01; rsp1 += s10 + s11; }
        *(u32*)(sm + sbuf + (m0 + r)     * 80 + ncol * 2) = pack_f16(s00, s01);
        *(u32*)(sm + sbuf + (m0 + r + 8) * 80 + ncol * 2) = pack_f16(s10, s11);
    };

    // ---- prologue: GEMM1(0) + transform(0) -> S buf0 ----
    CP_WAIT2();
    __syncthreads();
    {
        float cA[4] = {0.f, 0.f, 0.f, 0.f};
        float cB[4] = {0.f, 0.f, 0.f, 0.f};
        do_gemm1(smb + OF_STG, aQ, bT_off, cA, cB);
        transform(0, OF_S0, (const float*)(sm + OF_STG + ST_TN), cA, cB);
    }

    // ---- main pipelined loop: GEMM1(t+1) || GEMM2(t) ----
    int st1 = 1;                            // (t+1) % 3
    for (int t = 0; t < NTILES - 1; ++t) {
        CP_WAIT1();                         // tile t+1 data resident (own part)
        __syncthreads();                    // cross-warp: data + S visible

        const u32 stg_n = smb + OF_STG + (u32)st1 * STAGE;     // tile t+1
        int st0 = st1 - 1; if (st0 < 0) st0 = 2;               // t % 3
        const u32 stg_c = smb + OF_STG + (u32)st0 * STAGE;     // tile t

        // GEMM1(t+1) + transform -> S[(t+1)&1]
        {
            float cA[4] = {0.f, 0.f, 0.f, 0.f};
            float cB[4] = {0.f, 0.f, 0.f, 0.f};
            do_gemm1(stg_n, aQ, bT_off, cA, cB);
            transform(t + 1, OF_S0 + ((t + 1) & 1) * SBUFSZ,
                      (const float*)(sm + OF_STG + st1 * STAGE + ST_TN), cA, cB);
        }

        // GEMM2(t) from S[t&1]
        {
            const int sb = OF_S0 + (t & 1) * SBUFSZ;
            do_gemm2(stg_c, smb + sb + aS_off, bTT_off, acc);
        }

        // gen-phase boundary: dump accG + row sums
        if (t == GENTILES - 1) {
#pragma unroll
            for (int j = 0; j < 8; ++j) {
                int col = d0 + j * 8 + c0;
                *(float2*)(g_accG + (size_t)(row0 + m0 + r) * DIM + col) =
                    make_float2(acc[4*j], acc[4*j + 1]);
                *(float2*)(g_accG + (size_t)(row0 + m0 + r + 8) * DIM + col) =
                    make_float2(acc[4*j + 2], acc[4*j + 3]);
            }
            float a = rsg0 + __shfl_xor_sync(0xffffffffu, rsg0, 1);
            a += __shfl_xor_sync(0xffffffffu, a, 2);
            float b = rsg1 + __shfl_xor_sync(0xffffffffu, rsg1, 1);
            b += __shfl_xor_sync(0xffffffffu, b, 2);
            if ((lane & 3) == 0) {
                rsred[(m0 + r) * 4 + wn]     = a;
                rsred[(m0 + r + 8) * 4 + wn] = b;
            }
            __syncthreads();
            if (tid < BM)
                g_sg[row0 + tid] = rsred[tid*4] + rsred[tid*4+1]
                                 + rsred[tid*4+2] + rsred[tid*4+3];
#pragma unroll
            for (int i = 0; i < 32; ++i) acc[i] = 0.f;
        }

        __syncthreads();                    // all reads of stage t%3 done
        if (t + 3 < NTILES)
            prefetch(smb + OF_STG + (u32)st0 * STAGE, t + 3, tid);
        CP_COMMIT();

        st1++; if (st1 == 3) st1 = 0;
    }

    // ---- epilogue: GEMM2(last tile), reduce pos sums, write output ----
    {
        // tile 511 lives in stage (NTILES-1) % 3 == 1
        const u32 stg_c = smb + OF_STG + (u32)((NTILES - 1) % 3) * STAGE;
        const int sb = OF_S0 + ((NTILES - 1) & 1) * SBUFSZ;
        do_gemm2(stg_c, smb + sb + aS_off, bTT_off, acc);
    }
    {
        float a = rsp0 + __shfl_xor_sync(0xffffffffu, rsp0, 1);
        a += __shfl_xor_sync(0xffffffffu, a, 2);
        float b = rsp1 + __shfl_xor_sync(0xffffffffu, rsp1, 1);
        b += __shfl_xor_sync(0xffffffffu, b, 2);
        if ((lane & 3) == 0) {
            rsred[(m0 + r) * 4 + wn]     = a;
            rsred[(m0 + r + 8) * 4 + wn] = b;
        }
        __syncthreads();
        if (tid < BM)
            rsfin[tid] = rsred[tid*4] + rsred[tid*4+1]
                       + rsred[tid*4+2] + rsred[tid*4+3];
        __syncthreads();

        const float sp0 = rsfin[m0 + r];
        const float sp1 = rsfin[m0 + r + 8];
        const float sg0 = g_sg[row0 + m0 + r];
        const float sg1 = g_sg[row0 + m0 + r + 8];
#pragma unroll
        for (int j = 0; j < 8; ++j) {
            int col = d0 + j * 8 + c0;
            float2 gv0 = *(const float2*)(g_accG + (size_t)(row0 + m0 + r) * DIM + col);
            float2 gv1 = *(const float2*)(g_accG + (size_t)(row0 + m0 + r + 8) * DIM + col);
            float2 o0, o1;
            o0.x = sg0 * acc[4*j]     - sp0 * gv0.x;
            o0.y = sg0 * acc[4*j + 1] - sp0 * gv0.y;
            o1.x = sg1 * acc[4*j + 2] - sp1 * gv1.x;
            o1.y = sg1 * acc[4*j + 3] - sp1 * gv1.y;
            *(float2*)(out + (size_t)(row0 + m0 + r) * DIM + col)     = o0;
            *(float2*)(out + (size_t)(row0 + m0 + r + 8) * DIM + col) = o1;
        }
    }
}

// ---------------- launch ----------------
extern "C" void kernel_launch(void* const* d_in, const int* in_sizes, int n_in,
                              void* d_out, int out_size) {
    const float* G = (const float*)d_in[0];   // data_generated [8192,256]
    const float* P = (const float*)d_in[1];   // data_positive  [8192,256]
    float* out = (float*)d_out;               // [8192,256]

    cudaFuncSetAttribute(drift_main, cudaFuncAttributeMaxDynamicSharedMemorySize,
                         SMEM_SZ);

    prep_a<<<NT / 8, 256>>>(G, P);
    prep_tt<<<NTILES, 256>>>(G, P);
    drift_main<<<NCTA, NTHR, SMEM_SZ>>>(G, P, out);
}

// round 12
// speedup vs baseline: 7.1984x; 1.6351x over previous
#include <cuda_runtime.h>
#include <cuda_fp16.h>
#include <cstdint>

typedef uint32_t u32;

#define NGEN 8192
#define NT   16384
#define DIM  256
#define BM   64
#define BN   32
#define NTILES   512
#define GENTILES 256
#define NCTA     128
#define NTHR     512

// SMEM byte offsets
#define OF_Q    0                      // [64][264] f16 = 33792
#define OF_S0   33792                  // 2 x 5120 score ping-pong
#define SBUFSZ  5120
#define OF_RS   44032                  // [64][2] f32 = 512
#define OF_RF   44544                  // [64] f32 = 256
#define OF_STG  44800
#define ST_T    0                      // [32][264] f16 = 16896
#define ST_TT   16896                  // [256][40B] f16 = 20480
#define ST_TN   37376                  // 32 f32 = 128
#define STAGE   37504
#define SMEM_SZ (OF_STG + 4*STAGE)     // 194816

// ---------------- device scratch (static, no allocations) ----------------
__device__ float g_tnorm[NT];
__device__ float g_sg[NGEN];
__device__ __align__(16) unsigned char g_Tbf[(size_t)NT * 512];          // f16 rows
__device__ __align__(16) unsigned char g_Tth[(size_t)NTILES * 16384];    // [tile][256][16u32] f16 T^T
__device__ float g_accG[(size_t)NGEN * DIM];

// ---------------- asm helpers ----------------
__device__ __forceinline__ u32 smem_u32(const void* p) {
    u32 a; asm("{ .reg .u64 t; cvta.to.shared.u64 t, %1; cvt.u32.u64 %0, t; }"
               : "=r"(a) : "l"(p));
    return a;
}
__device__ __forceinline__ void ldsm4(u32 &r0, u32 &r1, u32 &r2, u32 &r3, u32 a) {
    asm volatile("ldmatrix.sync.aligned.m8n8.x4.shared.b16 {%0,%1,%2,%3}, [%4];"
                 : "=r"(r0), "=r"(r1), "=r"(r2), "=r"(r3) : "r"(a));
}
__device__ __forceinline__ void mma_f16(float* c, u32 a0, u32 a1, u32 a2, u32 a3,
                                        u32 b0, u32 b1) {
    asm volatile("mma.sync.aligned.m16n8k16.row.col.f32.f16.f16.f32 "
                 "{%0,%1,%2,%3}, {%4,%5,%6,%7}, {%8,%9}, {%0,%1,%2,%3};"
                 : "+f"(c[0]), "+f"(c[1]), "+f"(c[2]), "+f"(c[3])
                 : "r"(a0), "r"(a1), "r"(a2), "r"(a3), "r"(b0), "r"(b1));
}
__device__ __forceinline__ void cpa16(u32 s, const void* g) {
    asm volatile("cp.async.cg.shared.global [%0], [%1], 16;" :: "r"(s), "l"(g));
}
#define CP_COMMIT() asm volatile("cp.async.commit_group;" ::: "memory")
#define CP_WAIT1()  asm volatile("cp.async.wait_group 1;"  ::: "memory")
#define CP_WAIT2()  asm volatile("cp.async.wait_group 2;"  ::: "memory")
#define BARALL()    asm volatile("bar.sync 0, 512;" ::: "memory")
#define BARPROD()   asm volatile("bar.sync 1, 256;" ::: "memory")

__device__ __forceinline__ u32 pack_f16(float lo, float hi) {
    __half2 h = __floats2half2_rn(lo, hi);
    return *(u32*)&h;
}

// exp(-sqrt(sq)/20) entirely in FMA/ALU pipes (no MUFU)
__device__ __forceinline__ float score_fn(float sq, bool diag) {
    float y = __int_as_float(0x5f3759df - (__float_as_int(sq) >> 1));
    float xh = 0.5f * sq;
    y = y * (1.5f - xh * y * y);
    y = y * (1.5f - xh * y * y);
    float d  = sq * y;
    float tt = d * (-0.07213475204444817f);
    float k  = tt + 12582912.0f;
    int   n  = __float_as_int(k) - 0x4B400000;
    float f  = tt - (k - 12582912.0f);
    float p  = 1.3333558146e-3f;
    p = fmaf(p, f, 9.6181291076e-3f);
    p = fmaf(p, f, 5.5504108664e-2f);
    p = fmaf(p, f, 2.4022650696e-1f);
    p = fmaf(p, f, 6.9314718056e-1f);
    p = fmaf(p, f, 1.0f);
    float s = __int_as_float(__float_as_int(p) + (n << 23));
    if (!(sq > 1e-6f)) s = 1.0f;
    if (diag)          s = 0.0f;
    return s;
}

// ---------------- prep A: norms + f16 row image ----------------
__global__ void prep_a(const float* __restrict__ G, const float* __restrict__ P) {
    int gw   = (blockIdx.x * blockDim.x + threadIdx.x) >> 5;
    int lane = threadIdx.x & 31;
    if (gw >= NT) return;
    const float* row = (gw < NGEN) ? (G + (size_t)gw * DIM)
                                   : (P + (size_t)(gw - NGEN) * DIM);
    float4 a = ((const float4*)row)[lane * 2];
    float4 b = ((const float4*)row)[lane * 2 + 1];
    float s = a.x*a.x + a.y*a.y + a.z*a.z + a.w*a.w
            + b.x*b.x + b.y*b.y + b.z*b.z + b.w*b.w;
#pragma unroll
    for (int o = 16; o; o >>= 1) s += __shfl_xor_sync(0xffffffffu, s, o);
    if (lane == 0) g_tnorm[gw] = s;

    uint4 v;
    v.x = pack_f16(a.x, a.y);  v.y = pack_f16(a.z, a.w);
    v.z = pack_f16(b.x, b.y);  v.w = pack_f16(b.z, b.w);
    *(uint4*)(g_Tbf + (size_t)gw * 512 + lane * 16) = v;
}

// ---------------- prep B: transposed f16 tile images [256][32] ----------------
__global__ void prep_tt(const float* __restrict__ G, const float* __restrict__ P) {
    __shared__ float stage[32 * 264];
    int tile = blockIdx.x;
    int base = tile * BN;
    const float* src = (base < NGEN) ? (G + (size_t)base * DIM)
                                     : (P + (size_t)(base - NGEN) * DIM);
    int t = threadIdx.x;
#pragma unroll
    for (int k = 0; k < 8; ++k) {
        int idx = t + k * 256;
        int n = idx >> 6, dq = idx & 63;
        *(float4*)(stage + n * 264 + dq * 4) = *(const float4*)(src + (size_t)n * DIM + dq * 4);
    }
    __syncthreads();
    u32* oh = (u32*)g_Tth + (size_t)tile * 4096;
#pragma unroll
    for (int k = 0; k < 16; ++k) {
        int idx = t + k * 256;
        int d = idx >> 4, np = idx & 15, n = 2 * np;
        oh[d * 16 + np] = pack_f16(stage[n * 264 + d], stage[(n + 1) * 264 + d]);
    }
}

// ---------------- prefetch one tile into a stage ----------------
__device__ __forceinline__ void prefetch(u32 stg, int t2, int tid) {
    const unsigned char* srcT = g_Tbf + (size_t)t2 * BN * 512;
#pragma unroll
    for (int k = 0; k < 2; ++k) {
        int c = tid + k * 512;
        int n = c >> 5, part = c & 31;
        cpa16(stg + ST_T + n * 528 + part * 16, srcT + n * 512 + part * 16);
    }
    const unsigned char* srcH = g_Tth + (size_t)t2 * 16384;
#pragma unroll
    for (int k = 0; k < 2; ++k) {
        int c = tid + k * 512;
        int d = c >> 2, part = c & 3;
        cpa16(stg + ST_TT + d * 80 + part * 16, srcH + c * 16);
    }
    if (tid < 8)
        cpa16(stg + ST_TN + tid * 16,
              (const unsigned char*)g_tnorm + (size_t)t2 * 128 + tid * 16);
}

// ---------------- main fused kernel (warp-specialized) ----------------
__global__ void __launch_bounds__(NTHR, 1)
drift_main(const float* __restrict__ G, const float* __restrict__ P,
           float* __restrict__ out) {
    extern __shared__ unsigned char sm[];
    const u32 smb = smem_u32(sm);
    float* rsred = (float*)(sm + OF_RS);
    float* rsfin = (float*)(sm + OF_RF);

    const int tid  = threadIdx.x;
    const int lane = tid & 31;
    const int w    = tid >> 5;
    const int row0 = blockIdx.x * BM;
    const int r    = lane >> 2, c0 = 2 * (lane & 3);

    // convergent prologue: prefetch 0..2, Q fill, wait tile 0, sync
    prefetch(smb + OF_STG,             0, tid);  CP_COMMIT();
    prefetch(smb + OF_STG + STAGE,     1, tid);  CP_COMMIT();
    prefetch(smb + OF_STG + 2 * STAGE, 2, tid);  CP_COMMIT();
#pragma unroll
    for (int k = 0; k < 16; ++k) {
        int p = tid + k * 512;
        int m = p >> 7, dp = p & 127;
        float2 v = *(const float2*)(G + (size_t)(row0 + m) * DIM + 2 * dp);
        *(u32*)(sm + OF_Q + m * 528 + dp * 4) = pack_f16(v.x, v.y);
    }
    CP_WAIT2();
    __syncthreads();

    if (w < 8) {
        // ================= PRODUCER: GEMM1 + transform =================
        const int wm = w & 3, wn2 = w >> 2;          // 4 m-groups x 2 n-halves
        const int m0p = wm * 16, n0p = wn2 * 16;
        const u32 aQ   = smb + OF_Q + (m0p + (lane & 15)) * 528 + (lane >> 4) * 16;
        const u32 bTlo = (n0p + (lane & 7)) * 528 + ((lane >> 3) & 3) * 16;
        const u32 bThi = bTlo + 8 * 528;
        const float qn0 = g_tnorm[row0 + m0p + r];
        const float qn1 = g_tnorm[row0 + m0p + r + 8];

        // Q fragment cache: 16 k16-steps x 4 regs (invariant across tiles)
        u32 qf[64];
#pragma unroll
        for (int ks = 0; ks < 16; ++ks)
            ldsm4(qf[4*ks], qf[4*ks+1], qf[4*ks+2], qf[4*ks+3], aQ + ks * 32);

        float rsg0 = 0.f, rsg1 = 0.f, rsp0 = 0.f, rsp1 = 0.f;

        // one tile of GEMM1 + transform -> sbuf
        auto produce = [&](int tt, u32 stg, int sbuf) {
            float cl[4] = {0.f, 0.f, 0.f, 0.f};
            float ch[4] = {0.f, 0.f, 0.f, 0.f};
            const u32 bLo = stg + ST_T + bTlo;
            const u32 bHi = stg + ST_T + bThi;
#pragma unroll
            for (int kk = 0; kk < 8; ++kk) {         // k32 steps
                u32 l0, l1, l2, l3, h0, h1, h2, h3;
                ldsm4(l0, l1, l2, l3, bLo + kk * 64);
                ldsm4(h0, h1, h2, h3, bHi + kk * 64);
                mma_f16(cl, qf[8*kk],   qf[8*kk+1], qf[8*kk+2], qf[8*kk+3], l0, l1);
                mma_f16(cl, qf[8*kk+4], qf[8*kk+5], qf[8*kk+6], qf[8*kk+7], l2, l3);
                mma_f16(ch, qf[8*kk],   qf[8*kk+1], qf[8*kk+2], qf[8*kk+3], h0, h1);
                mma_f16(ch, qf[8*kk+4], qf[8*kk+5], qf[8*kk+6], qf[8*kk+7], h2, h3);
            }
            // transform
            const float* tnS = (const float*)(sm + (stg - smb) + ST_TN);
            const int tbase = tt * BN;
            const bool isGen = tt < GENTILES;
            const int nl = n0p + c0, nh = n0p + 8 + c0;
            float2 tl = *(const float2*)(tnS + nl);
            float2 th = *(const float2*)(tnS + nh);
            float sl00 = score_fn(qn0 + tl.x - 2.f * cl[0],
                                  isGen && (tbase + nl     == row0 + m0p + r));
            float sl01 = score_fn(qn0 + tl.y - 2.f * cl[1],
                                  isGen && (tbase + nl + 1 == row0 + m0p + r));
            float sl10 = score_fn(qn1 + tl.x - 2.f * cl[2],
                                  isGen && (tbase + nl     == row0 + m0p + r + 8));
            float sl11 = score_fn(qn1 + tl.y - 2.f * cl[3],
                                  isGen && (tbase + nl + 1 == row0 + m0p + r + 8));
            float sh00 = score_fn(qn0 + th.x - 2.f * ch[0],
                                  isGen && (tbase + nh     == row0 + m0p + r));
            float sh01 = score_fn(qn0 + th.y - 2.f * ch[1],
                                  isGen && (tbase + nh + 1 == row0 + m0p + r));
            float sh10 = score_fn(qn1 + th.x - 2.f * ch[2],
                                  isGen && (tbase + nh     == row0 + m0p + r + 8));
            float sh11 = score_fn(qn1 + th.y - 2.f * ch[3],
                                  isGen && (tbase + nh + 1 == row0 + m0p + r + 8));
            float a = sl00 + sl01 + sh00 + sh01;
            float b = sl10 + sl11 + sh10 + sh11;
            if (isGen) { rsg0 += a; rsg1 += b; }
            else       { rsp0 += a; rsp1 += b; }
            *(u32*)(sm + sbuf + (m0p + r)     * 80 + nl * 2) = pack_f16(sl00, sl01);
            *(u32*)(sm + sbuf + (m0p + r + 8) * 80 + nl * 2) = pack_f16(sl10, sl11);
            *(u32*)(sm + sbuf + (m0p + r)     * 80 + nh * 2) = pack_f16(sh00, sh01);
            *(u32*)(sm + sbuf + (m0p + r + 8) * 80 + nh * 2) = pack_f16(sh10, sh11);
        };

        // prologue: scores for tile 0
        produce(0, smb + OF_STG, OF_S0);

        for (int t = 0; t < NTILES - 1; ++t) {
            CP_WAIT1();
            BARALL();
            produce(t + 1, smb + OF_STG + (u32)((t + 1) & 3) * STAGE,
                    OF_S0 + ((t + 1) & 1) * SBUFSZ);

            if (t == GENTILES - 1) {   // gen row sums -> g_sg
                float a = rsg0 + __shfl_xor_sync(0xffffffffu, rsg0, 1);
                a += __shfl_xor_sync(0xffffffffu, a, 2);
                float b = rsg1 + __shfl_xor_sync(0xffffffffu, rsg1, 1);
                b += __shfl_xor_sync(0xffffffffu, b, 2);
                if ((lane & 3) == 0) {
                    rsred[(m0p + r) * 2 + wn2]     = a;
                    rsred[(m0p + r + 8) * 2 + wn2] = b;
                }
                BARPROD();
                if (wn2 == 0 && (lane & 3) == 0) {
                    int m = m0p + r;
                    g_sg[row0 + m] = rsred[m * 2] + rsred[m * 2 + 1];
                    m = m0p + r + 8;
                    g_sg[row0 + m] = rsred[m * 2] + rsred[m * 2 + 1];
                }
            }

            if (t + 3 < NTILES)
                prefetch(smb + OF_STG + (u32)((t + 3) & 3) * STAGE, t + 3, tid);
            CP_COMMIT();
        }

        // epilogue: match consumer barriers; reduce pos sums -> rsfin
        BARALL();
        {
            float a = rsp0 + __shfl_xor_sync(0xffffffffu, rsp0, 1);
            a += __shfl_xor_sync(0xffffffffu, a, 2);
            float b = rsp1 + __shfl_xor_sync(0xffffffffu, rsp1, 1);
            b += __shfl_xor_sync(0xffffffffu, b, 2);
            if ((lane & 3) == 0) {
                rsred[(m0p + r) * 2 + wn2]     = a;
                rsred[(m0p + r + 8) * 2 + wn2] = b;
            }
            BARPROD();
            if (wn2 == 0 && (lane & 3) == 0) {
                int m = m0p + r;
                rsfin[m] = rsred[m * 2] + rsred[m * 2 + 1];
                m = m0p + r + 8;
                rsfin[m] = rsred[m * 2] + rsred[m * 2 + 1];
            }
        }
        BARALL();
    } else {
        // ================= CONSUMER: GEMM2 =================
        const int cw = w - 8, mg = cw & 3, dh = cw >> 2; // 4 m-groups x 2 d-halves
        const int m0c = mg * 16;
        const u32 d0c = (u32)dh * 128;
        const u32 aS_off  = (m0c + (lane & 15)) * 80 + (lane >> 4) * 16;
        const u32 bTT_off = d0c * 80
                          + ((lane & 7) + ((lane >> 4) & 1) * 8) * 80
                          + ((lane >> 3) & 1) * 16;

        float acc[64];
#pragma unroll
        for (int i = 0; i < 64; ++i) acc[i] = 0.f;

        auto consume = [&](u32 stg, int sbuf) {
            u32 sh[8];
            ldsm4(sh[0], sh[1], sh[2], sh[3], smb + sbuf + aS_off);
            ldsm4(sh[4], sh[5], sh[6], sh[7], smb + sbuf + aS_off + 32);
            const u32 bH = stg + ST_TT + bTT_off;
#pragma unroll
            for (int j = 0; j < 8; ++j) {            // 16d chunks over 128d
#pragma unroll
                for (int kb = 0; kb < 2; ++kb) {
                    u32 h0, h1, h2, h3;
                    ldsm4(h0, h1, h2, h3, bH + j * 1280 + kb * 32);
                    mma_f16(acc + 8*j,     sh[4*kb], sh[4*kb+1], sh[4*kb+2], sh[4*kb+3], h0, h1);
                    mma_f16(acc + 8*j + 4, sh[4*kb], sh[4*kb+1], sh[4*kb+2], sh[4*kb+3], h2, h3);
                }
            }
        };

        for (int t = 0; t < NTILES - 1; ++t) {
            CP_WAIT1();
            BARALL();
            consume(smb + OF_STG + (u32)(t & 3) * STAGE, OF_S0 + (t & 1) * SBUFSZ);

            if (t == GENTILES - 1) {   // dump gen accumulator, reset
#pragma unroll
                for (int j = 0; j < 8; ++j) {
                    u32 col = d0c + j * 16 + c0;
                    float* ra = g_accG + (size_t)(row0 + m0c + r) * DIM + col;
                    float* rb = g_accG + (size_t)(row0 + m0c + r + 8) * DIM + col;
                    *(float2*)(ra)     = make_float2(acc[8*j],     acc[8*j + 1]);
                    *(float2*)(rb)     = make_float2(acc[8*j + 2], acc[8*j + 3]);
                    *(float2*)(ra + 8) = make_float2(acc[8*j + 4], acc[8*j + 5]);
                    *(float2*)(rb + 8) = make_float2(acc[8*j + 6], acc[8*j + 7]);
                }
#pragma unroll
                for (int i = 0; i < 64; ++i) acc[i] = 0.f;
            }

            if (t + 3 < NTILES)
                prefetch(smb + OF_STG + (u32)((t + 3) & 3) * STAGE, t + 3, tid);
            CP_COMMIT();
        }

        // epilogue: last tile, then combine
        BARALL();
        consume(smb + OF_STG + (u32)((NTILES - 1) & 3) * STAGE,
                OF_S0 + ((NTILES - 1) & 1) * SBUFSZ);
        BARALL();   // rsfin ready

        const float sp0 = rsfin[m0c + r];
        const float sp1 = rsfin[m0c + r + 8];
        const float sg0 = g_sg[row0 + m0c + r];
        const float sg1 = g_sg[row0 + m0c + r + 8];
#pragma unroll
        for (int j = 0; j < 8; ++j) {
            u32 col = d0c + j * 16 + c0;
            const float* ga = g_accG + (size_t)(row0 + m0c + r) * DIM + col;
            const float* gb = g_accG + (size_t)(row0 + m0c + r + 8) * DIM + col;
            float* oa = out + (size_t)(row0 + m0c + r) * DIM + col;
            float* ob = out + (size_t)(row0 + m0c + r + 8) * DIM + col;
            float2 g0 = *(const float2*)(ga), g0h = *(const float2*)(ga + 8);
            float2 g1 = *(const float2*)(gb), g1h = *(const float2*)(gb + 8);
            float2 o;
            o.x = sg0 * acc[8*j]     - sp0 * g0.x;
            o.y = sg0 * acc[8*j + 1] - sp0 * g0.y;
            *(float2*)(oa) = o;
            o.x = sg1 * acc[8*j + 2] - sp1 * g1.x;
            o.y = sg1 * acc[8*j + 3] - sp1 * g1.y;
            *(float2*)(ob) = o;
            o.x = sg0 * acc[8*j + 4] - sp0 * g0h.x;
            o.y = sg0 * acc[8*j + 5] - sp0 * g0h.y;
            *(float2*)(oa + 8) = o;
            o.x = sg1 * acc[8*j + 6] - sp1 * g1h.x;
            o.y = sg1 * acc[8*j + 7] - sp1 * g1h.y;
            *(float2*)(ob + 8) = o;
        }
    }
}

// ---------------- launch ----------------
extern "C" void kernel_launch(void* const* d_in, const int* in_sizes, int n_in,
                              void* d_out, int out_size) {
    const float* G = (const float*)d_in[0];   // data_generated [8192,256]
    const float* P = (const float*)d_in[1];   // data_positive  [8192,256]
    float* out = (float*)d_out;               // [8192,256]

    cudaFuncSetAttribute(drift_main, cudaFuncAttributeMaxDynamicSharedMemorySize,
                         SMEM_SZ);

    prep_a<<<NT / 8, 256>>>(G, P);
    prep_tt<<<NTILES, 256>>>(G, P);
    drift_main<<<NCTA, NTHR, SMEM_SZ>>>(G, P, out);
}

// round 13
// speedup vs baseline: 7.2003x; 1.0003x over previous
#include <cuda_runtime.h>
#include <cuda_fp16.h>
#include <cstdint>

typedef uint32_t u32;

#define NGEN 8192
#define NT   16384
#define DIM  256
#define BM   64
#define BN   32
#define NTILES   512
#define GENTILES 256
#define NCTA     128
#define NTHR     512

// SMEM byte offsets
#define OF_Q    0                      // [64][264] f16 = 33792
#define OF_S0   33792                  // 2 x 5120 score ping-pong
#define SBUFSZ  5120
#define OF_RS   44032                  // [64][2] f32 = 512
#define OF_RF   44544                  // [64] f32 = 256
#define OF_STG  44800
#define ST_T    0                      // [32][264] f16 = 16896
#define ST_TT   16896                  // [256][40B] f16 = 20480
#define ST_TN   37376                  // 32 f32 = 128
#define STAGE   37504
#define SMEM_SZ (OF_STG + 4*STAGE)     // 194816

// ---------------- device scratch (static, no allocations) ----------------
__device__ float g_tnorm[NT];
__device__ float g_sg[NGEN];
__device__ __align__(16) unsigned char g_Tbf[(size_t)NT * 512];          // f16 rows
__device__ __align__(16) unsigned char g_Tth[(size_t)NTILES * 16384];    // [tile][256][16u32] f16 T^T
__device__ float g_accG[(size_t)NGEN * DIM];

// ---------------- asm helpers ----------------
__device__ __forceinline__ u32 smem_u32(const void* p) {
    u32 a; asm("{ .reg .u64 t; cvta.to.shared.u64 t, %1; cvt.u32.u64 %0, t; }"
               : "=r"(a) : "l"(p));
    return a;
}
__device__ __forceinline__ void ldsm4(u32 &r0, u32 &r1, u32 &r2, u32 &r3, u32 a) {
    asm volatile("ldmatrix.sync.aligned.m8n8.x4.shared.b16 {%0,%1,%2,%3}, [%4];"
                 : "=r"(r0), "=r"(r1), "=r"(r2), "=r"(r3) : "r"(a));
}
__device__ __forceinline__ void mma_f16(float* c, u32 a0, u32 a1, u32 a2, u32 a3,
                                        u32 b0, u32 b1) {
    asm volatile("mma.sync.aligned.m16n8k16.row.col.f32.f16.f16.f32 "
                 "{%0,%1,%2,%3}, {%4,%5,%6,%7}, {%8,%9}, {%0,%1,%2,%3};"
                 : "+f"(c[0]), "+f"(c[1]), "+f"(c[2]), "+f"(c[3])
                 : "r"(a0), "r"(a1), "r"(a2), "r"(a3), "r"(b0), "r"(b1));
}
// f16-accumulator variant (2 C regs = 4 halves) — tests the 2x-rate hypothesis
__device__ __forceinline__ void mma_f16h(u32* c, u32 a0, u32 a1, u32 a2, u32 a3,
                                         u32 b0, u32 b1) {
    asm volatile("mma.sync.aligned.m16n8k16.row.col.f16.f16.f16.f16 "
                 "{%0,%1}, {%2,%3,%4,%5}, {%6,%7}, {%0,%1};"
                 : "+r"(c[0]), "+r"(c[1])
                 : "r"(a0), "r"(a1), "r"(a2), "r"(a3), "r"(b0), "r"(b1));
}
__device__ __forceinline__ void cpa16(u32 s, const void* g) {
    asm volatile("cp.async.cg.shared.global [%0], [%1], 16;" :: "r"(s), "l"(g));
}
#define CP_COMMIT() asm volatile("cp.async.commit_group;" ::: "memory")
#define CP_WAIT1()  asm volatile("cp.async.wait_group 1;"  ::: "memory")
#define CP_WAIT2()  asm volatile("cp.async.wait_group 2;"  ::: "memory")
#define BARALL()    asm volatile("bar.sync 0, 512;" ::: "memory")
#define BARPROD()   asm volatile("bar.sync 1, 256;" ::: "memory")

__device__ __forceinline__ u32 pack_f16(float lo, float hi) {
    __half2 h = __floats2half2_rn(lo, hi);
    return *(u32*)&h;
}
__device__ __forceinline__ float2 h2f2(u32 v) {
    __half2 h = *(__half2*)&v;
    return __half22float2(h);
}

// exp(-sqrt(sq)/20) entirely in FMA/ALU pipes (no MUFU)
__device__ __forceinline__ float score_fn(float sq, bool diag) {
    float y = __int_as_float(0x5f3759df - (__float_as_int(sq) >> 1));
    float xh = 0.5f * sq;
    y = y * (1.5f - xh * y * y);
    y = y * (1.5f - xh * y * y);
    float d  = sq * y;
    float tt = d * (-0.07213475204444817f);
    float k  = tt + 12582912.0f;
    int   n  = __float_as_int(k) - 0x4B400000;
    float f  = tt - (k - 12582912.0f);
    float p  = 1.3333558146e-3f;
    p = fmaf(p, f, 9.6181291076e-3f);
    p = fmaf(p, f, 5.5504108664e-2f);
    p = fmaf(p, f, 2.4022650696e-1f);
    p = fmaf(p, f, 6.9314718056e-1f);
    p = fmaf(p, f, 1.0f);
    float s = __int_as_float(__float_as_int(p) + (n << 23));
    if (!(sq > 1e-6f)) s = 1.0f;
    if (diag)          s = 0.0f;
    return s;
}

// ---------------- fused prep: norms + row image + transposed image ----------------
// One block per tile (512 blocks) so drift_main lands on ncu's -s 5 launch slot.
__global__ void prep_fused(const float* __restrict__ G, const float* __restrict__ P) {
    __shared__ float stage[32 * 264];
    int tile = blockIdx.x;
    int base = tile * BN;
    const float* src = (base < NGEN) ? (G + (size_t)base * DIM)
                                     : (P + (size_t)(base - NGEN) * DIM);
    int t = threadIdx.x;                  // 256 threads
#pragma unroll
    for (int k = 0; k < 8; ++k) {
        int idx = t + k * 256;
        int n = idx >> 6, dq = idx & 63;
        *(float4*)(stage + n * 264 + dq * 4) = *(const float4*)(src + (size_t)n * DIM + dq * 4);
    }
    __syncthreads();

    // norms: 8 threads per row, 32 elems each, xor-reduce within the 8-group
    {
        int row = t >> 3, seg = t & 7;
        const float* p = stage + row * 264 + seg * 32;
        float s = 0.f;
#pragma unroll
        for (int i = 0; i < 32; ++i) { float v = p[i]; s = fmaf(v, v, s); }
        s += __shfl_xor_sync(0xffffffffu, s, 1);
        s += __shfl_xor_sync(0xffffffffu, s, 2);
        s += __shfl_xor_sync(0xffffffffu, s, 4);
        if (seg == 0) g_tnorm[base + row] = s;
    }

    // f16 row image (K-major)
    u32* ob = (u32*)(g_Tbf + (size_t)base * 512);
#pragma unroll
    for (int k = 0; k < 16; ++k) {
        int idx = t + k * 256;            // 0..4095
        int row = idx >> 7, dp = idx & 127;
        ob[row * 128 + dp] = pack_f16(stage[row * 264 + 2 * dp],
                                      stage[row * 264 + 2 * dp + 1]);
    }

    // f16 transposed image [256 d][16 n-pairs]
    u32* oh = (u32*)g_Tth + (size_t)tile * 4096;
#pragma unroll
    for (int k = 0; k < 16; ++k) {
        int idx = t + k * 256;
        int d = idx >> 4, np = idx & 15, n = 2 * np;
        oh[d * 16 + np] = pack_f16(stage[n * 264 + d], stage[(n + 1) * 264 + d]);
    }
}

// ---------------- prefetch one tile into a stage ----------------
__device__ __forceinline__ void prefetch(u32 stg, int t2, int tid) {
    const unsigned char* srcT = g_Tbf + (size_t)t2 * BN * 512;
#pragma unroll
    for (int k = 0; k < 2; ++k) {
        int c = tid + k * 512;
        int n = c >> 5, part = c & 31;
        cpa16(stg + ST_T + n * 528 + part * 16, srcT + n * 512 + part * 16);
    }
    const unsigned char* srcH = g_Tth + (size_t)t2 * 16384;
#pragma unroll
    for (int k = 0; k < 2; ++k) {
        int c = tid + k * 512;
        int d = c >> 2, part = c & 3;
        cpa16(stg + ST_TT + d * 80 + part * 16, srcH + c * 16);
    }
    if (tid < 8)
        cpa16(stg + ST_TN + tid * 16,
              (const unsigned char*)g_tnorm + (size_t)t2 * 128 + tid * 16);
}

// ---------------- main fused kernel (warp-specialized) ----------------
__global__ void __launch_bounds__(NTHR, 1)
drift_main(const float* __restrict__ G, const float* __restrict__ P,
           float* __restrict__ out) {
    extern __shared__ unsigned char sm[];
    const u32 smb = smem_u32(sm);
    float* rsred = (float*)(sm + OF_RS);
    float* rsfin = (float*)(sm + OF_RF);

    const int tid  = threadIdx.x;
    const int lane = tid & 31;
    const int w    = tid >> 5;
    const int row0 = blockIdx.x * BM;
    const int r    = lane >> 2, c0 = 2 * (lane & 3);

    // convergent prologue: prefetch 0..2, Q fill, wait tile 0, sync
    prefetch(smb + OF_STG,             0, tid);  CP_COMMIT();
    prefetch(smb + OF_STG + STAGE,     1, tid);  CP_COMMIT();
    prefetch(smb + OF_STG + 2 * STAGE, 2, tid);  CP_COMMIT();
#pragma unroll
    for (int k = 0; k < 16; ++k) {
        int p = tid + k * 512;
        int m = p >> 7, dp = p & 127;
        float2 v = *(const float2*)(G + (size_t)(row0 + m) * DIM + 2 * dp);
        *(u32*)(sm + OF_Q + m * 528 + dp * 4) = pack_f16(v.x, v.y);
    }
    CP_WAIT2();
    __syncthreads();

    if (w < 8) {
        // ================= PRODUCER: GEMM1 (f16 acc) + transform =================
        const int wm = w & 3, wn2 = w >> 2;
        const int m0p = wm * 16, n0p = wn2 * 16;
        const u32 aQ   = smb + OF_Q + (m0p + (lane & 15)) * 528 + (lane >> 4) * 16;
        const u32 bTlo = (n0p + (lane & 7)) * 528 + ((lane >> 3) & 3) * 16;
        const u32 bThi = bTlo + 8 * 528;
        const float qn0 = g_tnorm[row0 + m0p + r];
        const float qn1 = g_tnorm[row0 + m0p + r + 8];

        // Q fragment cache: invariant across tiles
        u32 qf[64];
#pragma unroll
        for (int ks = 0; ks < 16; ++ks)
            ldsm4(qf[4*ks], qf[4*ks+1], qf[4*ks+2], qf[4*ks+3], aQ + ks * 32);

        float rsg0 = 0.f, rsg1 = 0.f, rsp0 = 0.f, rsp1 = 0.f;

        auto produce = [&](int tt, u32 stg, int sbuf) {
            // even/odd kk chains -> halves the serial HMMA dependency chain
            u32 cle[2] = {0u, 0u}, clo[2] = {0u, 0u};
            u32 che[2] = {0u, 0u}, cho[2] = {0u, 0u};
            const u32 bLo = stg + ST_T + bTlo;
            const u32 bHi = stg + ST_T + bThi;
#pragma unroll
            for (int kk = 0; kk < 8; ++kk) {
                u32 l0, l1, l2, l3, h0, h1, h2, h3;
                ldsm4(l0, l1, l2, l3, bLo + kk * 64);
                ldsm4(h0, h1, h2, h3, bHi + kk * 64);
                u32* cl = (kk & 1) ? clo : cle;
                u32* ch = (kk & 1) ? cho : che;
                mma_f16h(cl, qf[8*kk],   qf[8*kk+1], qf[8*kk+2], qf[8*kk+3], l0, l1);
                mma_f16h(cl, qf[8*kk+4], qf[8*kk+5], qf[8*kk+6], qf[8*kk+7], l2, l3);
                mma_f16h(ch, qf[8*kk],   qf[8*kk+1], qf[8*kk+2], qf[8*kk+3], h0, h1);
                mma_f16h(ch, qf[8*kk+4], qf[8*kk+5], qf[8*kk+6], qf[8*kk+7], h2, h3);
            }
            // combine even+odd chains in f32
            float2 e, o;
            e = h2f2(cle[0]); o = h2f2(clo[0]);
            float dl00 = e.x + o.x, dl01 = e.y + o.y;
            e = h2f2(cle[1]); o = h2f2(clo[1]);
            float dl10 = e.x + o.x, dl11 = e.y + o.y;
            e = h2f2(che[0]); o = h2f2(cho[0]);
            float dh00 = e.x + o.x, dh01 = e.y + o.y;
            e = h2f2(che[1]); o = h2f2(cho[1]);
            float dh10 = e.x + o.x, dh11 = e.y + o.y;

            // transform
            const float* tnS = (const float*)(sm + (stg - smb) + ST_TN);
            const int tbase = tt * BN;
            const bool isGen = tt < GENTILES;
            const int nl = n0p + c0, nh = n0p + 8 + c0;
            float2 tl = *(const float2*)(tnS + nl);
            float2 th = *(const float2*)(tnS + nh);
            float sl00 = score_fn(qn0 + tl.x - 2.f * dl00,
                                  isGen && (tbase + nl     == row0 + m0p + r));
            float sl01 = score_fn(qn0 + tl.y - 2.f * dl01,
                                  isGen && (tbase + nl + 1 == row0 + m0p + r));
            float sl10 = score_fn(qn1 + tl.x - 2.f * dl10,
                                  isGen && (tbase + nl     == row0 + m0p + r + 8));
            float sl11 = score_fn(qn1 + tl.y - 2.f * dl11,
                                  isGen && (tbase + nl + 1 == row0 + m0p + r + 8));
            float sh00 = score_fn(qn0 + th.x - 2.f * dh00,
                                  isGen && (tbase + nh     == row0 + m0p + r));
            float sh01 = score_fn(qn0 + th.y - 2.f * dh01,
                                  isGen && (tbase + nh + 1 == row0 + m0p + r));
            float sh10 = score_fn(qn1 + th.x - 2.f * dh10,
                                  isGen && (tbase + nh     == row0 + m0p + r + 8));
            float sh11 = score_fn(qn1 + th.y - 2.f * dh11,
                                  isGen && (tbase + nh + 1 == row0 + m0p + r + 8));
            float a = sl00 + sl01 + sh00 + sh01;
            float b = sl10 + sl11 + sh10 + sh11;
            if (isGen) { rsg0 += a; rsg1 += b; }
            else       { rsp0 += a; rsp1 += b; }
            *(u32*)(sm + sbuf + (m0p + r)     * 80 + nl * 2) = pack_f16(sl00, sl01);
            *(u32*)(sm + sbuf + (m0p + r + 8) * 80 + nl * 2) = pack_f16(sl10, sl11);
            *(u32*)(sm + sbuf + (m0p + r)     * 80 + nh * 2) = pack_f16(sh00, sh01);
            *(u32*)(sm + sbuf + (m0p + r + 8) * 80 + nh * 2) = pack_f16(sh10, sh11);
        };

        produce(0, smb + OF_STG, OF_S0);

        for (int t = 0; t < NTILES - 1; ++t) {
            CP_WAIT1();
            BARALL();
            produce(t + 1, smb + OF_STG + (u32)((t + 1) & 3) * STAGE,
                    OF_S0 + ((t + 1) & 1) * SBUFSZ);

            if (t == GENTILES - 1) {
                float a = rsg0 + __shfl_xor_sync(0xffffffffu, rsg0, 1);
                a += __shfl_xor_sync(0xffffffffu, a, 2);
                float b = rsg1 + __shfl_xor_sync(0xffffffffu, rsg1, 1);
                b += __shfl_xor_sync(0xffffffffu, b, 2);
                if ((lane & 3) == 0) {
                    rsred[(m0p + r) * 2 + wn2]     = a;
                    rsred[(m0p + r + 8) * 2 + wn2] = b;
                }
                BARPROD();
                if (wn2 == 0 && (lane & 3) == 0) {
                    int m = m0p + r;
                    g_sg[row0 + m] = rsred[m * 2] + rsred[m * 2 + 1];
                    m = m0p + r + 8;
                    g_sg[row0 + m] = rsred[m * 2] + rsred[m * 2 + 1];
                }
            }

            if (t + 3 < NTILES)
                prefetch(smb + OF_STG + (u32)((t + 3) & 3) * STAGE, t + 3, tid);
            CP_COMMIT();
        }

        BARALL();
        {
            float a = rsp0 + __shfl_xor_sync(0xffffffffu, rsp0, 1);
            a += __shfl_xor_sync(0xffffffffu, a, 2);
            float b = rsp1 + __shfl_xor_sync(0xffffffffu, rsp1, 1);
            b += __shfl_xor_sync(0xffffffffu, b, 2);
            if ((lane & 3) == 0) {
                rsred[(m0p + r) * 2 + wn2]     = a;
                rsred[(m0p + r + 8) * 2 + wn2] = b;
            }
            BARPROD();
            if (wn2 == 0 && (lane & 3) == 0) {
                int m = m0p + r;
                rsfin[m] = rsred[m * 2] + rsred[m * 2 + 1];
                m = m0p + r + 8;
                rsfin[m] = rsred[m * 2] + rsred[m * 2 + 1];
            }
        }
        BARALL();
    } else {
        // ================= CONSUMER: GEMM2 (f32 acc) =================
        const int cw = w - 8, mg = cw & 3, dh = cw >> 2;
        const int m0c = mg * 16;
        const u32 d0c = (u32)dh * 128;
        const u32 aS_off  = (m0c + (lane & 15)) * 80 + (lane >> 4) * 16;
        const u32 bTT_off = d0c * 80
                          + ((lane & 7) + ((lane >> 4) & 1) * 8) * 80
                          + ((lane >> 3) & 1) * 16;

        float acc[64];
#pragma unroll
        for (int i = 0; i < 64; ++i) acc[i] = 0.f;

        auto consume = [&](u32 stg, int sbuf) {
            u32 sh[8];
            ldsm4(sh[0], sh[1], sh[2], sh[3], smb + sbuf + aS_off);
            ldsm4(sh[4], sh[5], sh[6], sh[7], smb + sbuf + aS_off + 32);
            const u32 bH = stg + ST_TT + bTT_off;
#pragma unroll
            for (int j = 0; j < 8; ++j) {
#pragma unroll
                for (int kb = 0; kb < 2; ++kb) {
                    u32 h0, h1, h2, h3;
                    ldsm4(h0, h1, h2, h3, bH + j * 1280 + kb * 32);
                    mma_f16(acc + 8*j,     sh[4*kb], sh[4*kb+1], sh[4*kb+2], sh[4*kb+3], h0, h1);
                    mma_f16(acc + 8*j + 4, sh[4*kb], sh[4*kb+1], sh[4*kb+2], sh[4*kb+3], h2, h3);
                }
            }
        };

        for (int t = 0; t < NTILES - 1; ++t) {
            CP_WAIT1();
            BARALL();
            consume(smb + OF_STG + (u32)(t & 3) * STAGE, OF_S0 + (t & 1) * SBUFSZ);

            if (t == GENTILES - 1) {
#pragma unroll
                for (int j = 0; j < 8; ++j) {
                    u32 col = d0c + j * 16 + c0;
                    float* ra = g_accG + (size_t)(row0 + m0c + r) * DIM + col;
                    float* rb = g_accG + (size_t)(row0 + m0c + r + 8) * DIM + col;
                    *(float2*)(ra)     = make_float2(acc[8*j],     acc[8*j + 1]);
                    *(float2*)(rb)     = make_float2(acc[8*j + 2], acc[8*j + 3]);
                    *(float2*)(ra + 8) = make_float2(acc[8*j + 4], acc[8*j + 5]);
                    *(float2*)(rb + 8) = make_float2(acc[8*j + 6], acc[8*j + 7]);
                }
#pragma unroll
                for (int i = 0; i < 64; ++i) acc[i] = 0.f;
            }

            if (t + 3 < NTILES)
                prefetch(smb + OF_STG + (u32)((t + 3) & 3) * STAGE, t + 3, tid);
            CP_COMMIT();
        }

        BARALL();
        consume(smb + OF_STG + (u32)((NTILES - 1) & 3) * STAGE,
                OF_S0 + ((NTILES - 1) & 1) * SBUFSZ);
        BARALL();   // rsfin ready

        const float sp0 = rsfin[m0c + r];
        const float sp1 = rsfin[m0c + r + 8];
        const float sg0 = g_sg[row0 + m0c + r];
        const float sg1 = g_sg[row0 + m0c + r + 8];
#pragma unroll
        for (int j = 0; j < 8; ++j) {
            u32 col = d0c + j * 16 + c0;
            const float* ga = g_accG + (size_t)(row0 + m0c + r) * DIM + col;
            const float* gb = g_accG + (size_t)(row0 + m0c + r + 8) * DIM + col;
            float* oa = out + (size_t)(row0 + m0c + r) * DIM + col;
            float* ob = out + (size_t)(row0 + m0c + r + 8) * DIM + col;
            float2 g0 = *(const float2*)(ga), g0h = *(const float2*)(ga + 8);
            float2 g1 = *(const float2*)(gb), g1h = *(const float2*)(gb + 8);
            float2 o;
            o.x = sg0 * acc[8*j]     - sp0 * g0.x;
            o.y = sg0 * acc[8*j + 1] - sp0 * g0.y;
            *(float2*)(oa) = o;
            o.x = sg1 * acc[8*j + 2] - sp1 * g1.x;
            o.y = sg1 * acc[8*j + 3] - sp1 * g1.y;
            *(float2*)(ob) = o;
            o.x = sg0 * acc[8*j + 4] - sp0 * g0h.x;
            o.y = sg0 * acc[8*j + 5] - sp0 * g0h.y;
            *(float2*)(oa + 8) = o;
            o.x = sg1 * acc[8*j + 6] - sp1 * g1h.x;
            o.y = sg1 * acc[8*j + 7] - sp1 * g1h.y;
            *(float2*)(ob + 8) = o;
        }
    }
}

// ---------------- launch ----------------
extern "C" void kernel_launch(void* const* d_in, const int* in_sizes, int n_in,
                              void* d_out, int out_size) {
    const float* G = (const float*)d_in[0];   // data_generated [8192,256]
    const float* P = (const float*)d_in[1];   // data_positive  [8192,256]
    float* out = (float*)d_out;               // [8192,256]

    cudaFuncSetAttribute(drift_main, cudaFuncAttributeMaxDynamicSharedMemorySize,
                         SMEM_SZ);

    prep_fused<<<NTILES, 256>>>(G, P);
    drift_main<<<NCTA, NTHR, SMEM_SZ>>>(G, P, out);
}

// round 14
// speedup vs baseline: 7.8496x; 1.0902x over previous
#include <cuda_runtime.h>
#include <cuda_fp16.h>
#include <cstdint>

typedef uint32_t u32;

#define NGEN 8192
#define NT   16384
#define DIM  256
#define BM   64
#define BN   32
#define NTILES   512
#define GENTILES 256
#define NCTA     128
#define NTHR     512

// SMEM byte offsets
#define OF_Q    0                      // [64][264] f16 = 33792
#define OF_S0   33792                  // 2 x 5120 score ping-pong
#define SBUFSZ  5120
#define OF_RS   44032                  // [64][2] f32 = 512
#define OF_RF   44544                  // [64] f32 = 256
#define OF_STG  44800
#define ST_T    0                      // [32][264] f16 = 16896
#define ST_TT   16896                  // [256][40B] f16 = 20480
#define ST_TN   37376                  // 32 f32 = 128
#define STAGE   37504
#define SMEM_SZ (OF_STG + 4*STAGE)     // 194816

// ---------------- device scratch (static, no allocations) ----------------
__device__ float g_tnorm[NT];
__device__ float g_sg[NGEN];
__device__ __align__(16) unsigned char g_Tbf[(size_t)NT * 512];          // f16 rows
__device__ __align__(16) unsigned char g_Tth[(size_t)NTILES * 16384];    // [tile][256][16u32] f16 T^T
__device__ float g_accG[(size_t)NGEN * DIM];

// ---------------- asm helpers ----------------
__device__ __forceinline__ u32 smem_u32(const void* p) {
    u32 a; asm("{ .reg .u64 t; cvta.to.shared.u64 t, %1; cvt.u32.u64 %0, t; }"
               : "=r"(a) : "l"(p));
    return a;
}
__device__ __forceinline__ void ldsm4(u32 &r0, u32 &r1, u32 &r2, u32 &r3, u32 a) {
    asm volatile("ldmatrix.sync.aligned.m8n8.x4.shared.b16 {%0,%1,%2,%3}, [%4];"
                 : "=r"(r0), "=r"(r1), "=r"(r2), "=r"(r3) : "r"(a));
}
__device__ __forceinline__ void mma_f16(float* c, u32 a0, u32 a1, u32 a2, u32 a3,
                                        u32 b0, u32 b1) {
    asm volatile("mma.sync.aligned.m16n8k16.row.col.f32.f16.f16.f32 "
                 "{%0,%1,%2,%3}, {%4,%5,%6,%7}, {%8,%9}, {%0,%1,%2,%3};"
                 : "+f"(c[0]), "+f"(c[1]), "+f"(c[2]), "+f"(c[3])
                 : "r"(a0), "r"(a1), "r"(a2), "r"(a3), "r"(b0), "r"(b1));
}
__device__ __forceinline__ void cpa16(u32 s, const void* g) {
    asm volatile("cp.async.cg.shared.global [%0], [%1], 16;" :: "r"(s), "l"(g));
}
#define CP_COMMIT() asm volatile("cp.async.commit_group;" ::: "memory")
#define CP_WAIT1()  asm volatile("cp.async.wait_group 1;"  ::: "memory")
#define CP_WAIT2()  asm volatile("cp.async.wait_group 2;"  ::: "memory")
#define BARALL()    asm volatile("bar.sync 0, 512;" ::: "memory")
#define BARPROD()   asm volatile("bar.sync 1, 256;" ::: "memory")

__device__ __forceinline__ u32 pack_f16(float lo, float hi) {
    __half2 h = __floats2half2_rn(lo, hi);
    return *(u32*)&h;
}
__device__ __forceinline__ float fsqrt_ap(float x) {
    float r; asm("sqrt.approx.f32 %0, %1;" : "=f"(r) : "f"(x)); return r;
}
__device__ __forceinline__ float fex2_ap(float x) {
    float r; asm("ex2.approx.f32 %0, %1;" : "=f"(r) : "f"(x)); return r;
}

// exp(-sqrt(sq)/20) on the MUFU pipe: 2 MUFU + 2 FMA/ALU per score
__device__ __forceinline__ float score_fn(float sq, bool diag) {
    float sqc = fmaxf(sq, 0.f);                      // clip -> sqrt(0)=0 -> ex2(0)=1
    float s = fex2_ap(fsqrt_ap(sqc) * (-0.07213475204444817f));  // -log2(e)/20
    if (diag) s = 0.0f;                              // exp(-1e8/20) == 0
    return s;
}

// ---------------- fused prep: norms + row image + transposed image ----------------
__global__ void prep_fused(const float* __restrict__ G, const float* __restrict__ P) {
    __shared__ float stage[32 * 264];
    int tile = blockIdx.x;
    int base = tile * BN;
    const float* src = (base < NGEN) ? (G + (size_t)base * DIM)
                                     : (P + (size_t)(base - NGEN) * DIM);
    int t = threadIdx.x;                  // 256 threads
#pragma unroll
    for (int k = 0; k < 8; ++k) {
        int idx = t + k * 256;
        int n = idx >> 6, dq = idx & 63;
        *(float4*)(stage + n * 264 + dq * 4) = *(const float4*)(src + (size_t)n * DIM + dq * 4);
    }
    __syncthreads();

    // norms: 8 threads per row, 32 elems each, xor-reduce within the 8-group
    {
        int row = t >> 3, seg = t & 7;
        const float* p = stage + row * 264 + seg * 32;
        float s = 0.f;
#pragma unroll
        for (int i = 0; i < 32; ++i) { float v = p[i]; s = fmaf(v, v, s); }
        s += __shfl_xor_sync(0xffffffffu, s, 1);
        s += __shfl_xor_sync(0xffffffffu, s, 2);
        s += __shfl_xor_sync(0xffffffffu, s, 4);
        if (seg == 0) g_tnorm[base + row] = s;
    }

    // f16 row image (K-major)
    u32* ob = (u32*)(g_Tbf + (size_t)base * 512);
#pragma unroll
    for (int k = 0; k < 16; ++k) {
        int idx = t + k * 256;
        int row = idx >> 7, dp = idx & 127;
        ob[row * 128 + dp] = pack_f16(stage[row * 264 + 2 * dp],
                                      stage[row * 264 + 2 * dp + 1]);
    }

    // f16 transposed image [256 d][16 n-pairs]
    u32* oh = (u32*)g_Tth + (size_t)tile * 4096;
#pragma unroll
    for (int k = 0; k < 16; ++k) {
        int idx = t + k * 256;
        int d = idx >> 4, np = idx & 15, n = 2 * np;
        oh[d * 16 + np] = pack_f16(stage[n * 264 + d], stage[(n + 1) * 264 + d]);
    }
}

// ---------------- prefetch one tile into a stage ----------------
__device__ __forceinline__ void prefetch(u32 stg, int t2, int tid) {
    const unsigned char* srcT = g_Tbf + (size_t)t2 * BN * 512;
#pragma unroll
    for (int k = 0; k < 2; ++k) {
        int c = tid + k * 512;
        int n = c >> 5, part = c & 31;
        cpa16(stg + ST_T + n * 528 + part * 16, srcT + n * 512 + part * 16);
    }
    const unsigned char* srcH = g_Tth + (size_t)t2 * 16384;
#pragma unroll
    for (int k = 0; k < 2; ++k) {
        int c = tid + k * 512;
        int d = c >> 2, part = c & 3;
        cpa16(stg + ST_TT + d * 80 + part * 16, srcH + c * 16);
    }
    if (tid < 8)
        cpa16(stg + ST_TN + tid * 16,
              (const unsigned char*)g_tnorm + (size_t)t2 * 128 + tid * 16);
}

// ---------------- main fused kernel (warp-specialized) ----------------
__global__ void __launch_bounds__(NTHR, 1)
drift_main(const float* __restrict__ G, const float* __restrict__ P,
           float* __restrict__ out) {
    extern __shared__ unsigned char sm[];
    const u32 smb = smem_u32(sm);
    float* rsred = (float*)(sm + OF_RS);
    float* rsfin = (float*)(sm + OF_RF);

    const int tid  = threadIdx.x;
    const int lane = tid & 31;
    const int w    = tid >> 5;
    const int row0 = blockIdx.x * BM;
    const int r    = lane >> 2, c0 = 2 * (lane & 3);

    // convergent prologue: prefetch 0..2, Q fill, wait tile 0, sync
    prefetch(smb + OF_STG,             0, tid);  CP_COMMIT();
    prefetch(smb + OF_STG + STAGE,     1, tid);  CP_COMMIT();
    prefetch(smb + OF_STG + 2 * STAGE, 2, tid);  CP_COMMIT();
#pragma unroll
    for (int k = 0; k < 16; ++k) {
        int p = tid + k * 512;
        int m = p >> 7, dp = p & 127;
        float2 v = *(const float2*)(G + (size_t)(row0 + m) * DIM + 2 * dp);
        *(u32*)(sm + OF_Q + m * 528 + dp * 4) = pack_f16(v.x, v.y);
    }
    CP_WAIT2();
    __syncthreads();

    if (w < 8) {
        // ================= PRODUCER: GEMM1 (f32 acc) + MUFU transform =================
        const int wm = w & 3, wn2 = w >> 2;
        const int m0p = wm * 16, n0p = wn2 * 16;
        const u32 aQ   = smb + OF_Q + (m0p + (lane & 15)) * 528 + (lane >> 4) * 16;
        const u32 bTlo = (n0p + (lane & 7)) * 528 + ((lane >> 3) & 3) * 16;
        const u32 bThi = bTlo + 8 * 528;
        const float qn0 = g_tnorm[row0 + m0p + r];
        const float qn1 = g_tnorm[row0 + m0p + r + 8];

        // Q fragment cache: invariant across tiles
        u32 qf[64];
#pragma unroll
        for (int ks = 0; ks < 16; ++ks)
            ldsm4(qf[4*ks], qf[4*ks+1], qf[4*ks+2], qf[4*ks+3], aQ + ks * 32);

        float rsg0 = 0.f, rsg1 = 0.f, rsp0 = 0.f, rsp1 = 0.f;

        auto produce = [&](int tt, u32 stg, int sbuf) {
            float cl[4] = {0.f, 0.f, 0.f, 0.f};
            float ch[4] = {0.f, 0.f, 0.f, 0.f};
            const u32 bLo = stg + ST_T + bTlo;
            const u32 bHi = stg + ST_T + bThi;
            // ping-pong ldsm: load kk+1 frags before mma on kk
            u32 lA[4], hA[4], lB[4], hB[4];
            ldsm4(lA[0], lA[1], lA[2], lA[3], bLo);
            ldsm4(hA[0], hA[1], hA[2], hA[3], bHi);
#pragma unroll
            for (int kk = 0; kk < 8; ++kk) {
                u32* l = (kk & 1) ? lB : lA;
                u32* h = (kk & 1) ? hB : hA;
                u32* ln = (kk & 1) ? lA : lB;
                u32* hn = (kk & 1) ? hA : hB;
                if (kk < 7) {
                    ldsm4(ln[0], ln[1], ln[2], ln[3], bLo + (kk + 1) * 64);
                    ldsm4(hn[0], hn[1], hn[2], hn[3], bHi + (kk + 1) * 64);
                }
                mma_f16(cl, qf[8*kk],   qf[8*kk+1], qf[8*kk+2], qf[8*kk+3], l[0], l[1]);
                mma_f16(cl, qf[8*kk+4], qf[8*kk+5], qf[8*kk+6], qf[8*kk+7], l[2], l[3]);
                mma_f16(ch, qf[8*kk],   qf[8*kk+1], qf[8*kk+2], qf[8*kk+3], h[0], h[1]);
                mma_f16(ch, qf[8*kk+4], qf[8*kk+5], qf[8*kk+6], qf[8*kk+7], h[2], h[3]);
            }
            // transform (MUFU)
            const float* tnS = (const float*)(sm + (stg - smb) + ST_TN);
            const int tbase = tt * BN;
            const bool isGen = tt < GENTILES;
            const int nl = n0p + c0, nh = n0p + 8 + c0;
            float2 tl = *(const float2*)(tnS + nl);
            float2 th = *(const float2*)(tnS + nh);
            float sl00 = score_fn(qn0 + tl.x - 2.f * cl[0],
                                  isGen && (tbase + nl     == row0 + m0p + r));
            float sl01 = score_fn(qn0 + tl.y - 2.f * cl[1],
                                  isGen && (tbase + nl + 1 == row0 + m0p + r));
            float sl10 = score_fn(qn1 + tl.x - 2.f * cl[2],
                                  isGen && (tbase + nl     == row0 + m0p + r + 8));
            float sl11 = score_fn(qn1 + tl.y - 2.f * cl[3],
                                  isGen && (tbase + nl + 1 == row0 + m0p + r + 8));
            float sh00 = score_fn(qn0 + th.x - 2.f * ch[0],
                                  isGen && (tbase + nh     == row0 + m0p + r));
            float sh01 = score_fn(qn0 + th.y - 2.f * ch[1],
                                  isGen && (tbase + nh + 1 == row0 + m0p + r));
            float sh10 = score_fn(qn1 + th.x - 2.f * ch[2],
                                  isGen && (tbase + nh     == row0 + m0p + r + 8));
            float sh11 = score_fn(qn1 + th.y - 2.f * ch[3],
                                  isGen && (tbase + nh + 1 == row0 + m0p + r + 8));
            float a = sl00 + sl01 + sh00 + sh01;
            float b = sl10 + sl11 + sh10 + sh11;
            if (isGen) { rsg0 += a; rsg1 += b; }
            else       { rsp0 += a; rsp1 += b; }
            *(u32*)(sm + sbuf + (m0p + r)     * 80 + nl * 2) = pack_f16(sl00, sl01);
            *(u32*)(sm + sbuf + (m0p + r + 8) * 80 + nl * 2) = pack_f16(sl10, sl11);
            *(u32*)(sm + sbuf + (m0p + r)     * 80 + nh * 2) = pack_f16(sh00, sh01);
            *(u32*)(sm + sbuf + (m0p + r + 8) * 80 + nh * 2) = pack_f16(sh10, sh11);
        };

        produce(0, smb + OF_STG, OF_S0);

        for (int t = 0; t < NTILES - 1; ++t) {
            CP_WAIT1();
            BARALL();
            produce(t + 1, smb + OF_STG + (u32)((t + 1) & 3) * STAGE,
                    OF_S0 + ((t + 1) & 1) * SBUFSZ);

            if (t == GENTILES - 1) {
                float a = rsg0 + __shfl_xor_sync(0xffffffffu, rsg0, 1);
                a += __shfl_xor_sync(0xffffffffu, a, 2);
                float b = rsg1 + __shfl_xor_sync(0xffffffffu, rsg1, 1);
                b += __shfl_xor_sync(0xffffffffu, b, 2);
                if ((lane & 3) == 0) {
                    rsred[(m0p + r) * 2 + wn2]     = a;
                    rsred[(m0p + r + 8) * 2 + wn2] = b;
                }
                BARPROD();
                if (wn2 == 0 && (lane & 3) == 0) {
                    int m = m0p + r;
                    g_sg[row0 + m] = rsred[m * 2] + rsred[m * 2 + 1];
                    m = m0p + r + 8;
                    g_sg[row0 + m] = rsred[m * 2] + rsred[m * 2 + 1];
                }
            }

            if (t + 3 < NTILES)
                prefetch(smb + OF_STG + (u32)((t + 3) & 3) * STAGE, t + 3, tid);
            CP_COMMIT();
        }

        BARALL();
        {
            float a = rsp0 + __shfl_xor_sync(0xffffffffu, rsp0, 1);
            a += __shfl_xor_sync(0xffffffffu, a, 2);
            float b = rsp1 + __shfl_xor_sync(0xffffffffu, rsp1, 1);
            b += __shfl_xor_sync(0xffffffffu, b, 2);
            if ((lane & 3) == 0) {
                rsred[(m0p + r) * 2 + wn2]     = a;
                rsred[(m0p + r + 8) * 2 + wn2] = b;
            }
            BARPROD();
            if (wn2 == 0 && (lane & 3) == 0) {
                int m = m0p + r;
                rsfin[m] = rsred[m * 2] + rsred[m * 2 + 1];
                m = m0p + r + 8;
                rsfin[m] = rsred[m * 2] + rsred[m * 2 + 1];
            }
        }
        BARALL();
    } else {
        // ================= CONSUMER: GEMM2 (f32 acc) =================
        const int cw = w - 8, mg = cw & 3, dh = cw >> 2;
        const int m0c = mg * 16;
        const u32 d0c = (u32)dh * 128;
        const u32 aS_off  = (m0c + (lane & 15)) * 80 + (lane >> 4) * 16;
        const u32 bTT_off = d0c * 80
                          + ((lane & 7) + ((lane >> 4) & 1) * 8) * 80
                          + ((lane >> 3) & 1) * 16;

        float acc[64];
#pragma unroll
        for (int i = 0; i < 64; ++i) acc[i] = 0.f;

        auto consume = [&](u32 stg, int sbuf) {
            u32 sh[8];
            ldsm4(sh[0], sh[1], sh[2], sh[3], smb + sbuf + aS_off);
            ldsm4(sh[4], sh[5], sh[6], sh[7], smb + sbuf + aS_off + 32);
            const u32 bH = stg + ST_TT + bTT_off;
            // ping-pong ldsm over the 16 (j,kb) frags: i = 2j+kb
            u32 fA[4], fB[4];
            ldsm4(fA[0], fA[1], fA[2], fA[3], bH);
#pragma unroll
            for (int i = 0; i < 16; ++i) {
                u32* cur = (i & 1) ? fB : fA;
                u32* nxt = (i & 1) ? fA : fB;
                if (i < 15) {
                    int ni = i + 1;
                    ldsm4(nxt[0], nxt[1], nxt[2], nxt[3],
                          bH + (ni >> 1) * 1280 + (ni & 1) * 32);
                }
                int j = i >> 1, kb = i & 1;
                mma_f16(acc + 8*j,     sh[4*kb], sh[4*kb+1], sh[4*kb+2], sh[4*kb+3],
                        cur[0], cur[1]);
                mma_f16(acc + 8*j + 4, sh[4*kb], sh[4*kb+1], sh[4*kb+2], sh[4*kb+3],
                        cur[2], cur[3]);
            }
        };

        for (int t = 0; t < NTILES - 1; ++t) {
            CP_WAIT1();
            BARALL();
            consume(smb + OF_STG + (u32)(t & 3) * STAGE, OF_S0 + (t & 1) * SBUFSZ);

            if (t == GENTILES - 1) {
#pragma unroll
                for (int j = 0; j < 8; ++j) {
                    u32 col = d0c + j * 16 + c0;
                    float* ra = g_accG + (size_t)(row0 + m0c + r) * DIM + col;
                    float* rb = g_accG + (size_t)(row0 + m0c + r + 8) * DIM + col;
                    *(float2*)(ra)     = make_float2(acc[8*j],     acc[8*j + 1]);
                    *(float2*)(rb)     = make_float2(acc[8*j + 2], acc[8*j + 3]);
                    *(float2*)(ra + 8) = make_float2(acc[8*j + 4], acc[8*j + 5]);
                    *(float2*)(rb + 8) = make_float2(acc[8*j + 6], acc[8*j + 7]);
                }
#pragma unroll
                for (int i = 0; i < 64; ++i) acc[i] = 0.f;
            }

            if (t + 3 < NTILES)
                prefetch(smb + OF_STG + (u32)((t + 3) & 3) * STAGE, t + 3, tid);
            CP_COMMIT();
        }

        BARALL();
        consume(smb + OF_STG + (u32)((NTILES - 1) & 3) * STAGE,
                OF_S0 + ((NTILES - 1) & 1) * SBUFSZ);
        BARALL();   // rsfin ready

        const float sp0 = rsfin[m0c + r];
        const float sp1 = rsfin[m0c + r + 8];
        const float sg0 = g_sg[row0 + m0c + r];
        const float sg1 = g_sg[row0 + m0c + r + 8];
#pragma unroll
        for (int j = 0; j < 8; ++j) {
            u32 col = d0c + j * 16 + c0;
            const float* ga = g_accG + (size_t)(row0 + m0c + r) * DIM + col;
            const float* gb = g_accG + (size_t)(row0 + m0c + r + 8) * DIM + col;
            float* oa = out + (size_t)(row0 + m0c + r) * DIM + col;
            float* ob = out + (size_t)(row0 + m0c + r + 8) * DIM + col;
            float2 g0 = *(const float2*)(ga), g0h = *(const float2*)(ga + 8);
            float2 g1 = *(const float2*)(gb), g1h = *(const float2*)(gb + 8);
            float2 o;
            o.x = sg0 * acc[8*j]     - sp0 * g0.x;
            o.y = sg0 * acc[8*j + 1] - sp0 * g0.y;
            *(float2*)(oa) = o;
            o.x = sg1 * acc[8*j + 2] - sp1 * g1.x;
            o.y = sg1 * acc[8*j + 3] - sp1 * g1.y;
            *(float2*)(ob) = o;
            o.x = sg0 * acc[8*j + 4] - sp0 * g0h.x;
            o.y = sg0 * acc[8*j + 5] - sp0 * g0h.y;
            *(float2*)(oa + 8) = o;
            o.x = sg1 * acc[8*j + 6] - sp1 * g1h.x;
            o.y = sg1 * acc[8*j + 7] - sp1 * g1h.y;
            *(float2*)(ob + 8) = o;
        }
    }
}

// ---------------- launch ----------------
extern "C" void kernel_launch(void* const* d_in, const int* in_sizes, int n_in,
                              void* d_out, int out_size) {
    const float* G = (const float*)d_in[0];   // data_generated [8192,256]
    const float* P = (const float*)d_in[1];   // data_positive  [8192,256]
    float* out = (float*)d_out;               // [8192,256]

    cudaFuncSetAttribute(drift_main, cudaFuncAttributeMaxDynamicSharedMemorySize,
                         SMEM_SZ);

    prep_fused<<<NTILES, 256>>>(G, P);
    drift_main<<<NCTA, NTHR, SMEM_SZ>>>(G, P, out);
}